// round 11
// baseline (speedup 1.0000x reference)
#include <cuda_runtime.h>
#include <cuda_bf16.h>
#include <math.h>
#include <stdint.h>

#define NMAX 4096
#define DMAX 256
#define KPACK 768              // A pack: [hi|hi|lo]; B = chunk-permutation of A
#define SCALE_F 10.0f
#define EPS_F 1e-5f
#define INF_F __int_as_float(0x7f800000)
#define QSCALE 2048.0f         // d in [0,32) -> u16
#define QARG 0.0048828125f     // 10 / 2048
#define QSENT 0x7fffffff

__device__ float g_dist[(size_t)NMAX * NMAX];
__device__ float g_sq[NMAX];
__device__ unsigned char g_cam[NMAX];
__device__ float g_partial[NMAX];
__device__ int g_ctr = 0;
__device__ __nv_bfloat16 g_pa[(size_t)NMAX * KPACK];

__device__ __forceinline__ uint32_t smem_to_u32(const void* p) {
    uint32_t a;
    asm("{ .reg .u64 t; cvta.to.shared.u64 t, %1; cvt.u32.u64 %0, t; }"
        : "=r"(a) : "l"(p));
    return a;
}

#define LDMATRIX_X4(R, addr) \
    asm volatile("ldmatrix.sync.aligned.m8n8.x4.shared.b16 {%0,%1,%2,%3}, [%4];" \
        : "=r"((R)[0]), "=r"((R)[1]), "=r"((R)[2]), "=r"((R)[3]) : "r"(addr))
#define MMA_BF16(D, A, B) \
    asm volatile("mma.sync.aligned.m16n8k16.row.col.f32.bf16.bf16.f32 " \
        "{%0,%1,%2,%3}, {%4,%5,%6,%7}, {%8,%9}, {%0,%1,%2,%3};" \
        : "+f"((D)[0]), "+f"((D)[1]), "+f"((D)[2]), "+f"((D)[3]) \
        : "r"((A)[0]), "r"((A)[1]), "r"((A)[2]), "r"((A)[3]), \
          "r"((B)[0]), "r"((B)[1]))
#define CP_ASYNC16(dst, src) \
    asm volatile("cp.async.cg.shared.global [%0], [%1], 16;" \
        :: "r"(dst), "l"(src))
#define CP_COMMIT() asm volatile("cp.async.commit_group;")
#define CP_WAIT(N)  asm volatile("cp.async.wait_group %0;" :: "n"(N))

// ===========================================================================
// Fused prep: warp-per-row split+pack+sq  |  camid normalize (parallel probe)
// ===========================================================================
__global__ void prep_fused_kernel(const float* __restrict__ f,
                                  const int* __restrict__ cam_raw,
                                  int n, int d, int rowBlocks) {
    int b = blockIdx.x;
    if (b < rowBlocks) {
        int row  = b * 8 + (threadIdx.x >> 5);
        int lane = threadIdx.x & 31;
        if (row >= n) return;
        const float4* src = (const float4*)(f + (size_t)row * d) + lane * 2;
        float4 x0 = src[0], x1 = src[1];
        float xv[8] = {x0.x, x0.y, x0.z, x0.w, x1.x, x1.y, x1.z, x1.w};
        float s = 0.f;
        uint32_t hu[4], lu[4];
#pragma unroll
        for (int q = 0; q < 4; ++q) {
            float a = xv[2 * q], c = xv[2 * q + 1];
            s += a * a + c * c;
            __nv_bfloat16 h0 = __float2bfloat16_rn(a);
            __nv_bfloat16 h1 = __float2bfloat16_rn(c);
            __nv_bfloat16 l0 = __float2bfloat16_rn(a - __bfloat162float(h0));
            __nv_bfloat16 l1 = __float2bfloat16_rn(c - __bfloat162float(h1));
            __nv_bfloat162 hh(h0, h1), ll(l0, l1);
            hu[q] = *(uint32_t*)&hh;
            lu[q] = *(uint32_t*)&ll;
        }
#pragma unroll
        for (int off = 16; off; off >>= 1) s += __shfl_down_sync(0xffffffffu, s, off);
        if (lane == 0) g_sq[row] = s;

        uint4 hv = make_uint4(hu[0], hu[1], hu[2], hu[3]);
        uint4 lv = make_uint4(lu[0], lu[1], lu[2], lu[3]);
        uint4* pa4 = (uint4*)(g_pa + (size_t)row * KPACK);
        pa4[lane] = hv; pa4[32 + lane] = hv; pa4[64 + lane] = lv;
    } else {
        __shared__ int s_is64;
        int tid = threadIdx.x;
        if (tid < 32) {
            // parallel int64 probe: lane L checks ints 4L..4L+3 (pairs 2L,2L+1)
            int nz = 0;
            if (4 * tid + 3 < 2 * n) {
                uint4 w = ((const uint4*)cam_raw)[tid];
                nz = (w.y != 0) || (w.w != 0);   // odd words of 2 int64s
            }
            unsigned bal = __ballot_sync(0xffffffffu, nz);
            if (tid == 0) { s_is64 = (bal == 0); g_ctr = 0; }
        }
        __syncthreads();
        int is64 = s_is64;
        for (int j = tid; j < n; j += blockDim.x)
            g_cam[j] = (unsigned char)(is64 ? cam_raw[2 * j] : cam_raw[j]);
    }
}

// ===========================================================================
// Distance GEMM via mma.sync bf16, UPPER-TRIANGLE blocks only. (unchanged)
// ===========================================================================
#define NCHUNK (KPACK / 64)
#define BUF_BYTES 32768
#define TLDA 129
#define SMEM_GEMM_TOTAL (1024 + 3 * BUF_BYTES)

__global__ void __launch_bounds__(256, 2) dist_gemm_mma(int n) {
    extern __shared__ char smem_raw[];
    uint32_t sraw = smem_to_u32(smem_raw);
    uint32_t sbase = (sraw + 1023) & ~1023u;
    int tid = threadIdx.x, lane = tid & 31, wid = tid >> 5;

    int NB = n >> 7;
    int t = blockIdx.x;
    int bi = (int)((2.0f * NB + 1.0f -
                    sqrtf((2.0f * NB + 1.0f) * (2.0f * NB + 1.0f) - 8.0f * t)) * 0.5f);
    if (bi < 0) bi = 0;
    if (bi > NB - 1) bi = NB - 1;
#define TRI_START(r) ((r) * NB - ((r) * ((r) - 1)) / 2)
    while (bi + 1 < NB && TRI_START(bi + 1) <= t) ++bi;
    while (bi > 0 && TRI_START(bi) > t) --bi;
    int bj = bi + (t - TRI_START(bi));
#undef TRI_START

    const char* pa = (const char*)(g_pa + (size_t)bi * 128 * KPACK);
    const char* pb = (const char*)(g_pa + (size_t)bj * 128 * KPACK);
    const int ROWB = KPACK * 2;

    int seg = tid & 7, r0 = tid >> 3;

#define LOAD_CHUNK(c, buf) do { \
    int cb_ = ((c) < 4) ? (c) : (((c) < 8) ? (c) + 4 : (c) - 4); \
    uint32_t abase_ = sbase + (buf) * BUF_BYTES; \
    uint32_t bbase_ = abase_ + 16384; \
    _Pragma("unroll") \
    for (int it = 0; it < 4; ++it) { \
        int row = r0 + it * 32; \
        uint32_t off = row * 128 + seg * 16; \
        off = off ^ ((off >> 3) & 0x70); \
        CP_ASYNC16(abase_ + off, pa + (size_t)row * ROWB + (c) * 128 + seg * 16); \
        CP_ASYNC16(bbase_ + off, pb + (size_t)row * ROWB + cb_ * 128 + seg * 16); \
    } \
    CP_COMMIT(); \
} while (0)

    int wr = wid >> 2, wc = wid & 3;
    int wm = wr * 64, wn = wc * 32;

    float acc[4][4][4];
#pragma unroll
    for (int mt = 0; mt < 4; ++mt)
#pragma unroll
        for (int nt = 0; nt < 4; ++nt)
#pragma unroll
            for (int e = 0; e < 4; ++e) acc[mt][nt][e] = 0.f;

    LOAD_CHUNK(0, 0);
    LOAD_CHUNK(1, 1);
    for (int c = 0; c < NCHUNK; ++c) {
        if (c == NCHUNK - 1) CP_WAIT(0);
        else                 CP_WAIT(1);
        __syncthreads();
        if (c + 2 < NCHUNK) LOAD_CHUNK(c + 2, (c + 2) % 3);

        uint32_t abase = sbase + (c % 3) * BUF_BYTES;
        uint32_t bbase = abase + 16384;
#pragma unroll
        for (int kk = 0; kk < 4; ++kk) {
            uint32_t afr[4][4], bfr[4][2];
#pragma unroll
            for (int mt = 0; mt < 4; ++mt) {
                int row = wm + mt * 16 + (lane & 15);
                uint32_t off = row * 128 + kk * 32 + (lane >> 4) * 16;
                off = off ^ ((off >> 3) & 0x70);
                LDMATRIX_X4(afr[mt], abase + off);
            }
#pragma unroll
            for (int np = 0; np < 2; ++np) {
                int row = wn + np * 16 + ((lane >> 4) << 3) + (lane & 7);
                uint32_t off = row * 128 + kk * 32 + (((lane >> 3) & 1) << 4);
                off = off ^ ((off >> 3) & 0x70);
                uint32_t q[4];
                LDMATRIX_X4(q, bbase + off);
                bfr[np * 2 + 0][0] = q[0]; bfr[np * 2 + 0][1] = q[1];
                bfr[np * 2 + 1][0] = q[2]; bfr[np * 2 + 1][1] = q[3];
            }
#pragma unroll
            for (int mt = 0; mt < 4; ++mt)
#pragma unroll
                for (int nt = 0; nt < 4; ++nt)
                    MMA_BF16(acc[mt][nt], afr[mt], bfr[nt]);
        }
    }

    __shared__ float ssq[256];
    float* s_tile = (float*)(smem_raw + (sbase - sraw));
    if (tid < 128) ssq[tid] = g_sq[bi * 128 + tid];
    else           ssq[tid] = g_sq[bj * 128 + (tid - 128)];
    __syncthreads();

    int g4 = lane >> 2, t4 = lane & 3;
#pragma unroll
    for (int mt = 0; mt < 4; ++mt) {
#pragma unroll
        for (int half = 0; half < 2; ++half) {
            int r = wm + mt * 16 + g4 + half * 8;
            int gi = bi * 128 + r;
            float sqi = ssq[r];
#pragma unroll
            for (int nt = 0; nt < 4; ++nt) {
                int col = wn + nt * 8 + 2 * t4;
                int gj = bj * 128 + col;
                float2 o;
                float d0 = sqi + ssq[128 + col] + EPS_F
                           - 2.0f * acc[mt][nt][half * 2 + 0];
                float d1 = sqi + ssq[128 + col + 1] + EPS_F
                           - 2.0f * acc[mt][nt][half * 2 + 1];
                o.x = sqrtf(fmaxf(d0, 1e-12f));
                o.y = sqrtf(fmaxf(d1, 1e-12f));
                if (gi == gj)     o.x = sqrtf(EPS_F);
                if (gi == gj + 1) o.y = sqrtf(EPS_F);
                *(float2*)(g_dist + (size_t)gi * n + gj) = o;
                s_tile[r * TLDA + col]     = o.x;
                s_tile[r * TLDA + col + 1] = o.y;
            }
        }
    }

    if (bi != bj) {
        __syncthreads();
#pragma unroll
        for (int it = 0; it < 16; ++it) {
            int c = it * 8 + wid;
            float* orow = g_dist + (size_t)(bj * 128 + c) * n + bi * 128;
#pragma unroll
            for (int q = 0; q < 4; ++q) {
                int r = lane + q * 32;
                orow[r] = s_tile[r * TLDA + c];
            }
        }
    }
#undef LOAD_CHUNK
}

// ===========================================================================
// Row kernel v4: warp-per-row, u16-quantized smem cache, quantized-domain
// selection (exact ranks+ties within the quantized domain), single gmem pass.
// ===========================================================================
template <int N>
__device__ __forceinline__ void insertQ(int (&t)[N], int x) {
    if (x < t[N - 1]) {
        t[N - 1] = x;
#pragma unroll
        for (int k = N - 1; k > 0; --k) {
            int a = t[k - 1], b = t[k];
            t[k - 1] = min(a, b); t[k] = max(a, b);
        }
    }
}

template <int N>
__device__ __forceinline__ void warp_mergeQ(int (&t)[N], int lane, int (&out)[N]) {
#pragma unroll
    for (int r = 0; r < N; ++r) {
        int bv = t[0], bl = lane;
#pragma unroll
        for (int off = 16; off; off >>= 1) {
            int ov = __shfl_down_sync(0xffffffffu, bv, off);
            int ol = __shfl_down_sync(0xffffffffu, bl, off);
            if (ov < bv) { bv = ov; bl = ol; }
        }
        bv = __shfl_sync(0xffffffffu, bv, 0);
        bl = __shfl_sync(0xffffffffu, bl, 0);
        if (lane == bl) {
#pragma unroll
            for (int k = 0; k < N - 1; ++k) t[k] = t[k + 1];
            t[N - 1] = QSENT;
        }
        out[r] = bv;
    }
}

#define SMEM_ROW (8 * NMAX * 2 + NMAX + (8 + 256 + 4) * 4)

__global__ void __launch_bounds__(256) row_kernel(int n, int nCtas,
                                                  float* __restrict__ out) {
    extern __shared__ char sm[];
    unsigned short* s_q   = (unsigned short*)sm;                    // 8 x n u16
    unsigned char*  s_cam = (unsigned char*)(sm + 8 * NMAX * 2);    // n bytes
    float* s_part = (float*)(sm + 8 * NMAX * 2 + NMAX);
    float* s_red  = s_part + 8;
    int*   s_last = (int*)(s_red + 256);

    int tid = threadIdx.x, wid = tid >> 5, lane = tid & 31;
    int row = blockIdx.x * 8 + wid;

    for (int j = tid; j < n / 16; j += 256)
        ((uint4*)s_cam)[j] = ((const uint4*)g_cam)[j];
    __syncthreads();

    int mycam = s_cam[row];
    const float4* drow4 = (const float4*)(g_dist + (size_t)row * n);
    unsigned short* myq = s_q + wid * NMAX;
    int nIter = n >> 7;

    // ---- pass 1: quantize to smem + guarded integer inserts
    int t4I[4], t7E[7];
#pragma unroll
    for (int k = 0; k < 4; ++k) t4I[k] = QSENT;
#pragma unroll
    for (int k = 0; k < 7; ++k) t7E[k] = QSENT;

#pragma unroll 4
    for (int it = 0; it < nIter; ++it) {
        int j4 = it * 32 + lane;
        float4 f = drow4[j4];
        uchar4 cc = ((const uchar4*)s_cam)[j4];
        int jb = j4 << 2;
        int q0 = min(__float2int_rn(f.x * QSCALE), 65534);
        int q1 = min(__float2int_rn(f.y * QSCALE), 65534);
        int q2 = min(__float2int_rn(f.z * QSCALE), 65534);
        int q3 = min(__float2int_rn(f.w * QSCALE), 65534);
        if (jb     == row) q0 = 65535;     // self: excluded from lists; ~0 in sums
        if (jb + 1 == row) q1 = 65535;
        if (jb + 2 == row) q2 = 65535;
        if (jb + 3 == row) q3 = 65535;
        ushort4 st;
        st.x = (unsigned short)q0; st.y = (unsigned short)q1;
        st.z = (unsigned short)q2; st.w = (unsigned short)q3;
        ((ushort4*)myq)[j4] = st;
        int s0 = (q0 == 65535) ? QSENT : q0;
        int s1 = (q1 == 65535) ? QSENT : q1;
        int s2 = (q2 == 65535) ? QSENT : q2;
        int s3 = (q3 == 65535) ? QSENT : q3;
        if (cc.x == mycam) insertQ<4>(t4I, s0); else insertQ<7>(t7E, s0);
        if (cc.y == mycam) insertQ<4>(t4I, s1); else insertQ<7>(t7E, s1);
        if (cc.z == mycam) insertQ<4>(t4I, s2); else insertQ<7>(t7E, s2);
        if (cc.w == mycam) insertQ<4>(t4I, s3); else insertQ<7>(t7E, s3);
    }

    // ---- warp merges (integer domain)
    int mI[4], mEv[7];
    warp_mergeQ<4>(t4I, lane, mI);
    warp_mergeQ<7>(t7E, lane, mEv);
    int dKi = mI[3];     // combined intra rank 4 (self = rank 0, q=65535 > all real)
    int dKe = mEv[6], d0e = mEv[0];
    bool vI = dKi <= 65534, vE = dKe <= 65534;
    int cI = (mI[0] == dKi) + (mI[1] == dKi) + (mI[2] == dKi);
    int cE = (mEv[0] == dKe) + (mEv[1] == dKe) + (mEv[2] == dKe)
           + (mEv[3] == dKe) + (mEv[4] == dKe) + (mEv[5] == dKe);

    // ---- pass 2: exp sums from smem (u16), branchless
    float si = 0.f, se = 0.f;
    int dkI = vI ? dKi : -QSENT, dkE = vE ? dKe : -QSENT;  // invalid -> never include
#pragma unroll 4
    for (int it = 0; it < (nIter >> 1); ++it) {          // uint4 = 8 u16/lane
        int g = it * 32 + lane;
        uint4 qv = ((const uint4*)myq)[g];
        uchar4 c0 = ((const uchar4*)s_cam)[g * 2];
        uchar4 c1 = ((const uchar4*)s_cam)[g * 2 + 1];
        unsigned qs[4] = {qv.x, qv.y, qv.z, qv.w};
        unsigned char cs[8] = {c0.x, c0.y, c0.z, c0.w, c1.x, c1.y, c1.z, c1.w};
#pragma unroll
        for (int e = 0; e < 4; ++e) {
            int qa = (int)(qs[e] & 0xffffu);
            int qb = (int)(qs[e] >> 16);
            bool ma = (cs[2 * e]     == mycam);
            bool mb = (cs[2 * e + 1] == mycam);
            int da = (ma ? dkI : dkE) - qa;              // include iff da <= 0
            int db = (mb ? dkI : dkE) - qb;
            float ea = __expf((float)da * QARG);
            float eb = __expf((float)db * QARG);
            ea = (da <= 0) ? ea : 0.f;
            eb = (db <= 0) ? eb : 0.f;
            if (ma) si += ea; else se += ea;
            if (mb) si += eb; else se += eb;
        }
    }
#pragma unroll
    for (int off = 16; off; off >>= 1) {
        si += __shfl_xor_sync(0xffffffffu, si, off);
        se += __shfl_xor_sync(0xffffffffu, se, off);
    }

    if (lane == 0) {
        float term_i = 0.f, term_e = 0.f;
        if (vI) {
            float Si = si - (float)cI;                   // excluded-rank ties
            term_i = fmaxf(SCALE_F * sqrtf(EPS_F) - (float)dKi * QARG
                           + logf(Si) + 40.0f, 0.f);
        }
        if (vE) {
            float Se = se - (float)cE;
            term_e = fmaxf((float)(d0e - dKe) * QARG + logf(Se) + 6.0f, 0.f);
        }
        s_part[wid] = term_i + 0.5f * term_e;
    }
    __syncthreads();

    if (tid == 0) {
        float p = 0.f;
#pragma unroll
        for (int w = 0; w < 8; ++w) p += s_part[w];
        g_partial[blockIdx.x] = p;
        __threadfence();
        int old = atomicAdd(&g_ctr, 1);
        *s_last = (old == nCtas - 1);
    }
    __syncthreads();

    if (*s_last) {
        float s = 0.f;
        for (int j = tid; j < nCtas; j += 256) s += g_partial[j];
        s_red[tid] = s;
        __syncthreads();
        for (int st = 128; st; st >>= 1) {
            if (tid < st) s_red[tid] += s_red[tid + st];
            __syncthreads();
        }
        if (tid == 0) { out[0] = s_red[0] / (float)n; g_ctr = 0; }
    }
}

// ===========================================================================
extern "C" void kernel_launch(void* const* d_in, const int* in_sizes, int n_in,
                              void* d_out, int out_size) {
    const float* feat = (const float*)d_in[0];
    const int*   cam  = (const int*)d_in[1];
    int n = in_sizes[1];
    int d = in_sizes[0] / n;
    int NB = n / 128;

    static int smem_set = 0;
    if (!smem_set) {
        cudaFuncSetAttribute(dist_gemm_mma,
                             cudaFuncAttributeMaxDynamicSharedMemorySize,
                             SMEM_GEMM_TOTAL);
        cudaFuncSetAttribute(row_kernel,
                             cudaFuncAttributeMaxDynamicSharedMemorySize,
                             SMEM_ROW);
        smem_set = 1;
    }

    int rowBlocks = (n + 7) / 8;
    prep_fused_kernel<<<rowBlocks + 1, 256>>>(feat, cam, n, d, rowBlocks);
    dist_gemm_mma<<<NB * (NB + 1) / 2, 256, SMEM_GEMM_TOTAL>>>(n);
    int nCtas = n / 8;
    row_kernel<<<nCtas, 256, SMEM_ROW>>>(n, nCtas, (float*)d_out);
}

// round 12
// speedup vs baseline: 1.0971x; 1.0971x over previous
#include <cuda_runtime.h>
#include <cuda_bf16.h>
#include <math.h>
#include <stdint.h>

#define NMAX 4096
#define DMAX 256
#define KPACK 768              // A pack: [hi|hi|lo]; B = chunk-permutation of A
#define SCALE_F 10.0f
#define EPS_F 1e-5f
#define INF_F __int_as_float(0x7f800000)

__device__ float g_dist[(size_t)NMAX * NMAX];
__device__ float g_sq[NMAX];
__device__ unsigned char g_cam[NMAX];
__device__ float g_partial[NMAX];
__device__ int g_ctr = 0;
__device__ int g_tileq = 0;
__device__ int g_rowq = 0;
__device__ int g_ready[64];
__device__ __nv_bfloat16 g_pa[(size_t)NMAX * KPACK];

__device__ __forceinline__ uint32_t smem_to_u32(const void* p) {
    uint32_t a;
    asm("{ .reg .u64 t; cvta.to.shared.u64 t, %1; cvt.u32.u64 %0, t; }"
        : "=r"(a) : "l"(p));
    return a;
}

#define LDMATRIX_X4(R, addr) \
    asm volatile("ldmatrix.sync.aligned.m8n8.x4.shared.b16 {%0,%1,%2,%3}, [%4];" \
        : "=r"((R)[0]), "=r"((R)[1]), "=r"((R)[2]), "=r"((R)[3]) : "r"(addr))
#define MMA_BF16(D, A, B) \
    asm volatile("mma.sync.aligned.m16n8k16.row.col.f32.bf16.bf16.f32 " \
        "{%0,%1,%2,%3}, {%4,%5,%6,%7}, {%8,%9}, {%0,%1,%2,%3};" \
        : "+f"((D)[0]), "+f"((D)[1]), "+f"((D)[2]), "+f"((D)[3]) \
        : "r"((A)[0]), "r"((A)[1]), "r"((A)[2]), "r"((A)[3]), \
          "r"((B)[0]), "r"((B)[1]))
#define CP_ASYNC16(dst, src) \
    asm volatile("cp.async.cg.shared.global [%0], [%1], 16;" \
        :: "r"(dst), "l"(src))
#define CP_COMMIT() asm volatile("cp.async.commit_group;")
#define CP_WAIT(N)  asm volatile("cp.async.wait_group %0;" :: "n"(N))

// ===========================================================================
// Fused prep: warp-per-row split+pack+sq | camid normalize + counter resets
// ===========================================================================
__global__ void prep_fused_kernel(const float* __restrict__ f,
                                  const int* __restrict__ cam_raw,
                                  int n, int d, int rowBlocks) {
    int b = blockIdx.x;
    if (b < rowBlocks) {
        int row  = b * 8 + (threadIdx.x >> 5);
        int lane = threadIdx.x & 31;
        if (row >= n) return;
        const float4* src = (const float4*)(f + (size_t)row * d) + lane * 2;
        float4 x0 = src[0], x1 = src[1];
        float xv[8] = {x0.x, x0.y, x0.z, x0.w, x1.x, x1.y, x1.z, x1.w};
        float s = 0.f;
        uint32_t hu[4], lu[4];
#pragma unroll
        for (int q = 0; q < 4; ++q) {
            float a = xv[2 * q], c = xv[2 * q + 1];
            s += a * a + c * c;
            __nv_bfloat16 h0 = __float2bfloat16_rn(a);
            __nv_bfloat16 h1 = __float2bfloat16_rn(c);
            __nv_bfloat16 l0 = __float2bfloat16_rn(a - __bfloat162float(h0));
            __nv_bfloat16 l1 = __float2bfloat16_rn(c - __bfloat162float(h1));
            __nv_bfloat162 hh(h0, h1), ll(l0, l1);
            hu[q] = *(uint32_t*)&hh;
            lu[q] = *(uint32_t*)&ll;
        }
#pragma unroll
        for (int off = 16; off; off >>= 1) s += __shfl_down_sync(0xffffffffu, s, off);
        if (lane == 0) g_sq[row] = s;

        uint4 hv = make_uint4(hu[0], hu[1], hu[2], hu[3]);
        uint4 lv = make_uint4(lu[0], lu[1], lu[2], lu[3]);
        uint4* pa4 = (uint4*)(g_pa + (size_t)row * KPACK);
        pa4[lane] = hv; pa4[32 + lane] = hv; pa4[64 + lane] = lv;
    } else {
        __shared__ int s_is64;
        int tid = threadIdx.x;
        if (tid < 64) g_ready[tid] = 0;
        if (tid == 64) { g_tileq = 0; g_rowq = 0; g_ctr = 0; }
        if (tid < 32) {
            int nz = 0;
            if (4 * tid + 3 < 2 * n) {
                uint4 w = ((const uint4*)cam_raw)[tid];
                nz = (w.y != 0) || (w.w != 0);
            }
            unsigned bal = __ballot_sync(0xffffffffu, nz);
            if (tid == 0) s_is64 = (bal == 0);
        }
        __syncthreads();
        int is64 = s_is64;
        for (int j = tid; j < n; j += blockDim.x)
            g_cam[j] = (unsigned char)(is64 ? cam_raw[2 * j] : cam_raw[j]);
    }
}

// ===========================================================================
// Row helpers (R10 float versions)
// ===========================================================================
template <int N>
__device__ __forceinline__ void insertN(float (&t)[N], float x) {
    if (x < t[N - 1]) {
        t[N - 1] = x;
#pragma unroll
        for (int k = N - 1; k > 0; --k) {
            float a = t[k - 1], b = t[k];
            t[k - 1] = fminf(a, b); t[k] = fmaxf(a, b);
        }
    }
}

template <int N>
__device__ __forceinline__ void warp_merge(float (&t)[N], int lane, float (&out)[N]) {
#pragma unroll
    for (int r = 0; r < N; ++r) {
        float bv = t[0]; int bl = lane;
#pragma unroll
        for (int off = 16; off; off >>= 1) {
            float ov = __shfl_down_sync(0xffffffffu, bv, off);
            int   ol = __shfl_down_sync(0xffffffffu, bl, off);
            if (ov < bv) { bv = ov; bl = ol; }
        }
        bv = __shfl_sync(0xffffffffu, bv, 0);
        bl = __shfl_sync(0xffffffffu, bl, 0);
        if (lane == bl) {
#pragma unroll
            for (int k = 0; k < N - 1; ++k) t[k] = t[k + 1];
            t[N - 1] = INF_F;
        }
        out[r] = bv;
    }
}

// ===========================================================================
// FUSED persistent kernel: GEMM tile queue -> row-group queue with per-block
// readiness. Grid = 2 * SM count (all CTAs resident -> no deadlock).
// ===========================================================================
#define NCHUNK (KPACK / 64)
#define BUF_BYTES 32768
#define TLDA 129
#define SMEM_FUSED (1024 + 3 * BUF_BYTES)

__global__ void __launch_bounds__(256, 2) fused_kernel(int n, int nTiles,
                                                       int nGroups,
                                                       float* __restrict__ out) {
    extern __shared__ char smem_raw[];
    uint32_t sraw = smem_to_u32(smem_raw);
    uint32_t sbase = (sraw + 1023) & ~1023u;
    __shared__ float ssq[256];
    __shared__ int   s_job;
    __shared__ float s_part[8];
    __shared__ float s_red[256];
    __shared__ int   s_last;

    int tid = threadIdx.x, lane = tid & 31, wid = tid >> 5;
    int NB = n >> 7;
    const int ROWB = KPACK * 2;
    int seg = tid & 7, r0 = tid >> 3;
    int wr = wid >> 2, wc = wid & 3;
    int wm = wr * 64, wn = wc * 32;

    // ================= phase 1: GEMM tiles =================
    for (;;) {
        if (tid == 0) s_job = atomicAdd(&g_tileq, 1);
        __syncthreads();
        int t = s_job;
        __syncthreads();
        if (t >= nTiles) break;

        // triangular decode
        int bi = (int)((2.0f * NB + 1.0f -
                        sqrtf((2.0f * NB + 1.0f) * (2.0f * NB + 1.0f) - 8.0f * t)) * 0.5f);
        if (bi < 0) bi = 0;
        if (bi > NB - 1) bi = NB - 1;
#define TRI_START(r) ((r) * NB - ((r) * ((r) - 1)) / 2)
        while (bi + 1 < NB && TRI_START(bi + 1) <= t) ++bi;
        while (bi > 0 && TRI_START(bi) > t) --bi;
        int bj = bi + (t - TRI_START(bi));
#undef TRI_START

        const char* pa = (const char*)(g_pa + (size_t)bi * 128 * KPACK);
        const char* pb = (const char*)(g_pa + (size_t)bj * 128 * KPACK);

#define LOAD_CHUNK(c, buf) do { \
    int cb_ = ((c) < 4) ? (c) : (((c) < 8) ? (c) + 4 : (c) - 4); \
    uint32_t abase_ = sbase + (buf) * BUF_BYTES; \
    uint32_t bbase_ = abase_ + 16384; \
    _Pragma("unroll") \
    for (int it = 0; it < 4; ++it) { \
        int row = r0 + it * 32; \
        uint32_t off = row * 128 + seg * 16; \
        off = off ^ ((off >> 3) & 0x70); \
        CP_ASYNC16(abase_ + off, pa + (size_t)row * ROWB + (c) * 128 + seg * 16); \
        CP_ASYNC16(bbase_ + off, pb + (size_t)row * ROWB + cb_ * 128 + seg * 16); \
    } \
    CP_COMMIT(); \
} while (0)

        float acc[4][4][4];
#pragma unroll
        for (int mt = 0; mt < 4; ++mt)
#pragma unroll
            for (int nt = 0; nt < 4; ++nt)
#pragma unroll
                for (int e = 0; e < 4; ++e) acc[mt][nt][e] = 0.f;

        LOAD_CHUNK(0, 0);
        LOAD_CHUNK(1, 1);
        for (int c = 0; c < NCHUNK; ++c) {
            if (c == NCHUNK - 1) CP_WAIT(0);
            else                 CP_WAIT(1);
            __syncthreads();
            if (c + 2 < NCHUNK) LOAD_CHUNK(c + 2, (c + 2) % 3);

            uint32_t abase = sbase + (c % 3) * BUF_BYTES;
            uint32_t bbase = abase + 16384;
#pragma unroll
            for (int kk = 0; kk < 4; ++kk) {
                uint32_t afr[4][4], bfr[4][2];
#pragma unroll
                for (int mt = 0; mt < 4; ++mt) {
                    int row = wm + mt * 16 + (lane & 15);
                    uint32_t off = row * 128 + kk * 32 + (lane >> 4) * 16;
                    off = off ^ ((off >> 3) & 0x70);
                    LDMATRIX_X4(afr[mt], abase + off);
                }
#pragma unroll
                for (int np = 0; np < 2; ++np) {
                    int row = wn + np * 16 + ((lane >> 4) << 3) + (lane & 7);
                    uint32_t off = row * 128 + kk * 32 + (((lane >> 3) & 1) << 4);
                    off = off ^ ((off >> 3) & 0x70);
                    uint32_t q[4];
                    LDMATRIX_X4(q, bbase + off);
                    bfr[np * 2 + 0][0] = q[0]; bfr[np * 2 + 0][1] = q[1];
                    bfr[np * 2 + 1][0] = q[2]; bfr[np * 2 + 1][1] = q[3];
                }
#pragma unroll
                for (int mt = 0; mt < 4; ++mt)
#pragma unroll
                    for (int nt = 0; nt < 4; ++nt)
                        MMA_BF16(acc[mt][nt], afr[mt], bfr[nt]);
            }
        }
#undef LOAD_CHUNK

        float* s_tile = (float*)(smem_raw + (sbase - sraw));
        if (tid < 128) ssq[tid] = g_sq[bi * 128 + tid];
        else           ssq[tid] = g_sq[bj * 128 + (tid - 128)];
        __syncthreads();

        int g4 = lane >> 2, t4 = lane & 3;
#pragma unroll
        for (int mt = 0; mt < 4; ++mt) {
#pragma unroll
            for (int half = 0; half < 2; ++half) {
                int r = wm + mt * 16 + g4 + half * 8;
                int gi = bi * 128 + r;
                float sqi = ssq[r];
#pragma unroll
                for (int nt = 0; nt < 4; ++nt) {
                    int col = wn + nt * 8 + 2 * t4;
                    int gj = bj * 128 + col;
                    float2 o;
                    float d0 = sqi + ssq[128 + col] + EPS_F
                               - 2.0f * acc[mt][nt][half * 2 + 0];
                    float d1 = sqi + ssq[128 + col + 1] + EPS_F
                               - 2.0f * acc[mt][nt][half * 2 + 1];
                    o.x = sqrtf(fmaxf(d0, 1e-12f));
                    o.y = sqrtf(fmaxf(d1, 1e-12f));
                    if (gi == gj)     o.x = sqrtf(EPS_F);
                    if (gi == gj + 1) o.y = sqrtf(EPS_F);
                    *(float2*)(g_dist + (size_t)gi * n + gj) = o;
                    s_tile[r * TLDA + col]     = o.x;
                    s_tile[r * TLDA + col + 1] = o.y;
                }
            }
        }

        if (bi != bj) {
            __syncthreads();
#pragma unroll
            for (int it = 0; it < 16; ++it) {
                int c = it * 8 + wid;
                float* orow = g_dist + (size_t)(bj * 128 + c) * n + bi * 128;
#pragma unroll
                for (int q = 0; q < 4; ++q) {
                    int r = lane + q * 32;
                    orow[r] = s_tile[r * TLDA + c];
                }
            }
        }

        __syncthreads();                   // all stores of this tile issued
        if (tid == 0) {
            __threadfence();
            atomicAdd(&g_ready[bi], 1);
            if (bi != bj) atomicAdd(&g_ready[bj], 1);
        }
        __syncthreads();
    }

    // ================= phase 2: row groups =================
    unsigned char* s_cam = (unsigned char*)smem_raw;   // reuse dynamic smem
    for (int j = tid; j < n / 16; j += 256)
        ((uint4*)s_cam)[j] = ((const uint4*)g_cam)[j];
    __syncthreads();

    for (;;) {
        if (tid == 0) s_job = atomicAdd(&g_rowq, 1);
        __syncthreads();
        int g = s_job;
        __syncthreads();
        if (g >= nGroups) break;
        int rb = g >> 4;                    // block-row (16 groups of 8 per 128)

        if (tid == 0) {
            while (*((volatile int*)&g_ready[rb]) < NB) __nanosleep(128);
        }
        __syncthreads();
        __threadfence();                    // acquire published dist

        int row = g * 8 + wid;
        int mycam = s_cam[row];
        const float4* drow4 = (const float4*)(g_dist + (size_t)row * n);
        int nIter = n >> 7;

        float t4I[4], t7E[7];
#pragma unroll
        for (int k = 0; k < 4; ++k) t4I[k] = INF_F;
#pragma unroll
        for (int k = 0; k < 7; ++k) t7E[k] = INF_F;

#pragma unroll 4
        for (int it = 0; it < nIter; ++it) {
            int j4 = it * 32 + lane;
            float4 f = drow4[j4];
            uchar4 cc = ((const uchar4*)s_cam)[j4];
            int jb = j4 << 2;
            float x0 = (jb     == row) ? INF_F : f.x;
            float x1 = (jb + 1 == row) ? INF_F : f.y;
            float x2 = (jb + 2 == row) ? INF_F : f.z;
            float x3 = (jb + 3 == row) ? INF_F : f.w;
            if (cc.x == mycam) insertN<4>(t4I, x0); else insertN<7>(t7E, x0);
            if (cc.y == mycam) insertN<4>(t4I, x1); else insertN<7>(t7E, x1);
            if (cc.z == mycam) insertN<4>(t4I, x2); else insertN<7>(t7E, x2);
            if (cc.w == mycam) insertN<4>(t4I, x3); else insertN<7>(t7E, x3);
        }

        float mI[4], mEv[7];
        warp_merge<4>(t4I, lane, mI);
        warp_merge<7>(t7E, lane, mEv);
        float dKi = mI[3];                 // combined intra rank 4 (self=rank 0)
        float d0e = mEv[0], dKe = mEv[6];

        float si = 0.f, se = 0.f;
#pragma unroll 4
        for (int it = 0; it < nIter; ++it) {
            int j4 = it * 32 + lane;
            float4 f = drow4[j4];
            uchar4 cc = ((const uchar4*)s_cam)[j4];
            int jb = j4 << 2;
            float x0 = (jb     == row) ? INF_F : f.x;
            float x1 = (jb + 1 == row) ? INF_F : f.y;
            float x2 = (jb + 2 == row) ? INF_F : f.z;
            float x3 = (jb + 3 == row) ? INF_F : f.w;
#define ACC1(cm, xx) do { \
            bool m_ = (cm == mycam); \
            float dk_ = m_ ? dKi : dKe; \
            float e_ = __expf(SCALE_F * (dk_ - (xx))); \
            e_ = ((xx) >= dk_) ? e_ : 0.f; \
            if (m_) si += e_; else se += e_; } while (0)
            ACC1(cc.x, x0); ACC1(cc.y, x1); ACC1(cc.z, x2); ACC1(cc.w, x3);
#undef ACC1
        }
#pragma unroll
        for (int off = 16; off; off >>= 1) {
            si += __shfl_xor_sync(0xffffffffu, si, off);
            se += __shfl_xor_sync(0xffffffffu, se, off);
        }

        if (lane == 0) {
            float d0i = sqrtf(EPS_F);
            float term_i = 0.f, term_e = 0.f;
            if (isfinite(dKi))
                term_i = fmaxf(SCALE_F * (d0i - dKi) + logf(si) + 40.0f, 0.f);
            if (isfinite(dKe))
                term_e = fmaxf(SCALE_F * (d0e - dKe) + logf(se) + 6.0f, 0.f);
            s_part[wid] = term_i + 0.5f * term_e;
        }
        __syncthreads();

        if (tid == 0) {
            float p = 0.f;
#pragma unroll
            for (int w = 0; w < 8; ++w) p += s_part[w];
            g_partial[g] = p;
            __threadfence();
            int old = atomicAdd(&g_ctr, 1);
            s_last = (old == nGroups - 1);
        }
        __syncthreads();

        if (s_last) {
            float s = 0.f;
            for (int j = tid; j < nGroups; j += 256) s += g_partial[j];
            s_red[tid] = s;
            __syncthreads();
            for (int st = 128; st; st >>= 1) {
                if (tid < st) s_red[tid] += s_red[tid + st];
                __syncthreads();
            }
            if (tid == 0) out[0] = s_red[0] / (float)n;
            break;
        }
        __syncthreads();
    }
}

// ===========================================================================
extern "C" void kernel_launch(void* const* d_in, const int* in_sizes, int n_in,
                              void* d_out, int out_size) {
    const float* feat = (const float*)d_in[0];
    const int*   cam  = (const int*)d_in[1];
    int n = in_sizes[1];
    int d = in_sizes[0] / n;
    int NB = n / 128;

    static int nSM = 0;
    if (!nSM) {
        cudaFuncSetAttribute(fused_kernel,
                             cudaFuncAttributeMaxDynamicSharedMemorySize,
                             SMEM_FUSED);
        int dev = 0;
        cudaGetDevice(&dev);
        cudaDeviceGetAttribute(&nSM, cudaDevAttrMultiProcessorCount, dev);
        if (nSM <= 0) nSM = 148;
    }

    int rowBlocks = (n + 7) / 8;
    prep_fused_kernel<<<rowBlocks + 1, 256>>>(feat, cam, n, d, rowBlocks);
    int nTiles = NB * (NB + 1) / 2;
    int nGroups = n / 8;
    fused_kernel<<<2 * nSM, 256, SMEM_FUSED>>>(n, nTiles, nGroups,
                                               (float*)d_out);
}

// round 13
// speedup vs baseline: 1.1777x; 1.0735x over previous
#include <cuda_runtime.h>
#include <cuda_bf16.h>
#include <math.h>
#include <stdint.h>

#define NMAX 4096
#define DMAX 256
#define KPACK 768              // A pack: [hi|hi|lo]; B = chunk-permutation of A
#define SCALE_F 10.0f
#define EPS_F 1e-5f
#define INF_F __int_as_float(0x7f800000)

__device__ float g_dist[(size_t)NMAX * NMAX];
__device__ float g_sq[NMAX];
__device__ unsigned char g_cam[NMAX];
__device__ float g_partial[NMAX];
__device__ int g_ctr = 0;
__device__ __nv_bfloat16 g_pa[(size_t)NMAX * KPACK];

__device__ __forceinline__ uint32_t smem_to_u32(const void* p) {
    uint32_t a;
    asm("{ .reg .u64 t; cvta.to.shared.u64 t, %1; cvt.u32.u64 %0, t; }"
        : "=r"(a) : "l"(p));
    return a;
}

#define LDMATRIX_X4(R, addr) \
    asm volatile("ldmatrix.sync.aligned.m8n8.x4.shared.b16 {%0,%1,%2,%3}, [%4];" \
        : "=r"((R)[0]), "=r"((R)[1]), "=r"((R)[2]), "=r"((R)[3]) : "r"(addr))
#define MMA_BF16(D, A, B) \
    asm volatile("mma.sync.aligned.m16n8k16.row.col.f32.bf16.bf16.f32 " \
        "{%0,%1,%2,%3}, {%4,%5,%6,%7}, {%8,%9}, {%0,%1,%2,%3};" \
        : "+f"((D)[0]), "+f"((D)[1]), "+f"((D)[2]), "+f"((D)[3]) \
        : "r"((A)[0]), "r"((A)[1]), "r"((A)[2]), "r"((A)[3]), \
          "r"((B)[0]), "r"((B)[1]))
#define CP_ASYNC16(dst, src) \
    asm volatile("cp.async.cg.shared.global [%0], [%1], 16;" \
        :: "r"(dst), "l"(src))
#define CP_COMMIT() asm volatile("cp.async.commit_group;")
#define CP_WAIT(N)  asm volatile("cp.async.wait_group %0;" :: "n"(N))

// ===========================================================================
// Fused prep: warp-per-row split+pack+sq | camid normalize + counter reset
// ===========================================================================
__global__ void prep_fused_kernel(const float* __restrict__ f,
                                  const int* __restrict__ cam_raw,
                                  int n, int d, int rowBlocks) {
    int b = blockIdx.x;
    if (b < rowBlocks) {
        int row  = b * 8 + (threadIdx.x >> 5);
        int lane = threadIdx.x & 31;
        if (row >= n) return;
        const float4* src = (const float4*)(f + (size_t)row * d) + lane * 2;
        float4 x0 = src[0], x1 = src[1];
        float xv[8] = {x0.x, x0.y, x0.z, x0.w, x1.x, x1.y, x1.z, x1.w};
        float s = 0.f;
        uint32_t hu[4], lu[4];
#pragma unroll
        for (int q = 0; q < 4; ++q) {
            float a = xv[2 * q], c = xv[2 * q + 1];
            s += a * a + c * c;
            __nv_bfloat16 h0 = __float2bfloat16_rn(a);
            __nv_bfloat16 h1 = __float2bfloat16_rn(c);
            __nv_bfloat16 l0 = __float2bfloat16_rn(a - __bfloat162float(h0));
            __nv_bfloat16 l1 = __float2bfloat16_rn(c - __bfloat162float(h1));
            __nv_bfloat162 hh(h0, h1), ll(l0, l1);
            hu[q] = *(uint32_t*)&hh;
            lu[q] = *(uint32_t*)&ll;
        }
#pragma unroll
        for (int off = 16; off; off >>= 1) s += __shfl_down_sync(0xffffffffu, s, off);
        if (lane == 0) g_sq[row] = s;

        uint4 hv = make_uint4(hu[0], hu[1], hu[2], hu[3]);
        uint4 lv = make_uint4(lu[0], lu[1], lu[2], lu[3]);
        uint4* pa4 = (uint4*)(g_pa + (size_t)row * KPACK);
        pa4[lane] = hv; pa4[32 + lane] = hv; pa4[64 + lane] = lv;
    } else {
        __shared__ int s_is64;
        int tid = threadIdx.x;
        if (tid < 32) {
            int nz = 0;
            if (4 * tid + 3 < 2 * n) {
                uint4 w = ((const uint4*)cam_raw)[tid];
                nz = (w.y != 0) || (w.w != 0);
            }
            unsigned bal = __ballot_sync(0xffffffffu, nz);
            if (tid == 0) { s_is64 = (bal == 0); g_ctr = 0; }
        }
        __syncthreads();
        int is64 = s_is64;
        for (int j = tid; j < n; j += blockDim.x)
            g_cam[j] = (unsigned char)(is64 ? cam_raw[2 * j] : cam_raw[j]);
    }
}

// ===========================================================================
// Distance GEMM via mma.sync bf16, UPPER-TRIANGLE blocks only. (R10 version)
// ===========================================================================
#define NCHUNK (KPACK / 64)
#define BUF_BYTES 32768
#define TLDA 129
#define SMEM_GEMM_TOTAL (1024 + 3 * BUF_BYTES)

__global__ void __launch_bounds__(256, 2) dist_gemm_mma(int n) {
    extern __shared__ char smem_raw[];
    uint32_t sraw = smem_to_u32(smem_raw);
    uint32_t sbase = (sraw + 1023) & ~1023u;
    int tid = threadIdx.x, lane = tid & 31, wid = tid >> 5;

    int NB = n >> 7;
    int t = blockIdx.x;
    int bi = (int)((2.0f * NB + 1.0f -
                    sqrtf((2.0f * NB + 1.0f) * (2.0f * NB + 1.0f) - 8.0f * t)) * 0.5f);
    if (bi < 0) bi = 0;
    if (bi > NB - 1) bi = NB - 1;
#define TRI_START(r) ((r) * NB - ((r) * ((r) - 1)) / 2)
    while (bi + 1 < NB && TRI_START(bi + 1) <= t) ++bi;
    while (bi > 0 && TRI_START(bi) > t) --bi;
    int bj = bi + (t - TRI_START(bi));
#undef TRI_START

    const char* pa = (const char*)(g_pa + (size_t)bi * 128 * KPACK);
    const char* pb = (const char*)(g_pa + (size_t)bj * 128 * KPACK);
    const int ROWB = KPACK * 2;

    int seg = tid & 7, r0 = tid >> 3;

#define LOAD_CHUNK(c, buf) do { \
    int cb_ = ((c) < 4) ? (c) : (((c) < 8) ? (c) + 4 : (c) - 4); \
    uint32_t abase_ = sbase + (buf) * BUF_BYTES; \
    uint32_t bbase_ = abase_ + 16384; \
    _Pragma("unroll") \
    for (int it = 0; it < 4; ++it) { \
        int row = r0 + it * 32; \
        uint32_t off = row * 128 + seg * 16; \
        off = off ^ ((off >> 3) & 0x70); \
        CP_ASYNC16(abase_ + off, pa + (size_t)row * ROWB + (c) * 128 + seg * 16); \
        CP_ASYNC16(bbase_ + off, pb + (size_t)row * ROWB + cb_ * 128 + seg * 16); \
    } \
    CP_COMMIT(); \
} while (0)

    int wr = wid >> 2, wc = wid & 3;
    int wm = wr * 64, wn = wc * 32;

    float acc[4][4][4];
#pragma unroll
    for (int mt = 0; mt < 4; ++mt)
#pragma unroll
        for (int nt = 0; nt < 4; ++nt)
#pragma unroll
            for (int e = 0; e < 4; ++e) acc[mt][nt][e] = 0.f;

    LOAD_CHUNK(0, 0);
    LOAD_CHUNK(1, 1);
    for (int c = 0; c < NCHUNK; ++c) {
        if (c == NCHUNK - 1) CP_WAIT(0);
        else                 CP_WAIT(1);
        __syncthreads();
        if (c + 2 < NCHUNK) LOAD_CHUNK(c + 2, (c + 2) % 3);

        uint32_t abase = sbase + (c % 3) * BUF_BYTES;
        uint32_t bbase = abase + 16384;
#pragma unroll
        for (int kk = 0; kk < 4; ++kk) {
            uint32_t afr[4][4], bfr[4][2];
#pragma unroll
            for (int mt = 0; mt < 4; ++mt) {
                int row = wm + mt * 16 + (lane & 15);
                uint32_t off = row * 128 + kk * 32 + (lane >> 4) * 16;
                off = off ^ ((off >> 3) & 0x70);
                LDMATRIX_X4(afr[mt], abase + off);
            }
#pragma unroll
            for (int np = 0; np < 2; ++np) {
                int row = wn + np * 16 + ((lane >> 4) << 3) + (lane & 7);
                uint32_t off = row * 128 + kk * 32 + (((lane >> 3) & 1) << 4);
                off = off ^ ((off >> 3) & 0x70);
                uint32_t q[4];
                LDMATRIX_X4(q, bbase + off);
                bfr[np * 2 + 0][0] = q[0]; bfr[np * 2 + 0][1] = q[1];
                bfr[np * 2 + 1][0] = q[2]; bfr[np * 2 + 1][1] = q[3];
            }
#pragma unroll
            for (int mt = 0; mt < 4; ++mt)
#pragma unroll
                for (int nt = 0; nt < 4; ++nt)
                    MMA_BF16(acc[mt][nt], afr[mt], bfr[nt]);
        }
    }

    __shared__ float ssq[256];
    float* s_tile = (float*)(smem_raw + (sbase - sraw));
    if (tid < 128) ssq[tid] = g_sq[bi * 128 + tid];
    else           ssq[tid] = g_sq[bj * 128 + (tid - 128)];
    __syncthreads();

    int g4 = lane >> 2, t4 = lane & 3;
#pragma unroll
    for (int mt = 0; mt < 4; ++mt) {
#pragma unroll
        for (int half = 0; half < 2; ++half) {
            int r = wm + mt * 16 + g4 + half * 8;
            int gi = bi * 128 + r;
            float sqi = ssq[r];
#pragma unroll
            for (int nt = 0; nt < 4; ++nt) {
                int col = wn + nt * 8 + 2 * t4;
                int gj = bj * 128 + col;
                float2 o;
                float d0 = sqi + ssq[128 + col] + EPS_F
                           - 2.0f * acc[mt][nt][half * 2 + 0];
                float d1 = sqi + ssq[128 + col + 1] + EPS_F
                           - 2.0f * acc[mt][nt][half * 2 + 1];
                o.x = sqrtf(fmaxf(d0, 1e-12f));
                o.y = sqrtf(fmaxf(d1, 1e-12f));
                if (gi == gj)     o.x = sqrtf(EPS_F);
                if (gi == gj + 1) o.y = sqrtf(EPS_F);
                *(float2*)(g_dist + (size_t)gi * n + gj) = o;
                s_tile[r * TLDA + col]     = o.x;
                s_tile[r * TLDA + col + 1] = o.y;
            }
        }
    }

    if (bi != bj) {
        __syncthreads();
#pragma unroll
        for (int it = 0; it < 16; ++it) {
            int c = it * 8 + wid;
            float* orow = g_dist + (size_t)(bj * 128 + c) * n + bi * 128;
#pragma unroll
            for (int q = 0; q < 4; ++q) {
                int r = lane + q * 32;
                orow[r] = s_tile[r * TLDA + c];
            }
        }
    }
#undef LOAD_CHUNK
}

// ===========================================================================
// Row kernel v5: TWO warps per row (2048 elems each) -> 8192 warps total for
// full occupancy. Halves combined via closed-form order statistics on the
// two sorted per-warp lists (static indices only).
// ===========================================================================
template <int N>
__device__ __forceinline__ void insertN(float (&t)[N], float x) {
    if (x < t[N - 1]) {
        t[N - 1] = x;
#pragma unroll
        for (int k = N - 1; k > 0; --k) {
            float a = t[k - 1], b = t[k];
            t[k - 1] = fminf(a, b); t[k] = fmaxf(a, b);
        }
    }
}

template <int N>
__device__ __forceinline__ void warp_merge(float (&t)[N], int lane, float (&out)[N]) {
#pragma unroll
    for (int r = 0; r < N; ++r) {
        float bv = t[0]; int bl = lane;
#pragma unroll
        for (int off = 16; off; off >>= 1) {
            float ov = __shfl_down_sync(0xffffffffu, bv, off);
            int   ol = __shfl_down_sync(0xffffffffu, bl, off);
            if (ov < bv) { bv = ov; bl = ol; }
        }
        bv = __shfl_sync(0xffffffffu, bv, 0);
        bl = __shfl_sync(0xffffffffu, bl, 0);
        if (lane == bl) {
#pragma unroll
            for (int k = 0; k < N - 1; ++k) t[k] = t[k + 1];
            t[N - 1] = INF_F;
        }
        out[r] = bv;
    }
}

// merged[3] of two sorted 4-lists
__device__ __forceinline__ float merged3(const float* A, const float* B) {
    float m = B[3];
    m = fminf(m, fmaxf(A[0], B[2]));
    m = fminf(m, fmaxf(A[1], B[1]));
    m = fminf(m, fmaxf(A[2], B[0]));
    m = fminf(m, A[3]);
    return m;
}
// merged[6] of two sorted 7-lists
__device__ __forceinline__ float merged6(const float* A, const float* B) {
    float m = B[6];
    m = fminf(m, fmaxf(A[0], B[5]));
    m = fminf(m, fmaxf(A[1], B[4]));
    m = fminf(m, fmaxf(A[2], B[3]));
    m = fminf(m, fmaxf(A[3], B[2]));
    m = fminf(m, fmaxf(A[4], B[1]));
    m = fminf(m, fmaxf(A[5], B[0]));
    m = fminf(m, A[6]);
    return m;
}

__global__ void __launch_bounds__(256) row_kernel(int n, int nCtas,
                                                  float* __restrict__ out) {
    __shared__ unsigned char s_cam[NMAX];
    __shared__ float s_lists[8][12];     // per warp: [0..3] intra, [4..10] inter
    __shared__ float s_sums[8][2];
    __shared__ float s_part[4];
    __shared__ float s_red[256];
    __shared__ int   s_last;

    int tid = threadIdx.x, wid = tid >> 5, lane = tid & 31;
    int rowLocal = wid >> 1, half = wid & 1;
    int row = blockIdx.x * 4 + rowLocal;

    for (int j = tid; j < n / 16; j += 256)
        ((uint4*)s_cam)[j] = ((const uint4*)g_cam)[j];
    __syncthreads();

    int mycam = s_cam[row];
    const float4* drow4 = (const float4*)(g_dist + (size_t)row * n);
    int itBeg = half * 16, itEnd = itBeg + 16;   // 16 iters x 128 elems

    // ---- pass 1: guarded inserts over this half's 2048 elements
    float t4I[4], t7E[7];
#pragma unroll
    for (int k = 0; k < 4; ++k) t4I[k] = INF_F;
#pragma unroll
    for (int k = 0; k < 7; ++k) t7E[k] = INF_F;

#pragma unroll 4
    for (int it = itBeg; it < itEnd; ++it) {
        int j4 = it * 32 + lane;
        float4 f = drow4[j4];
        uchar4 cc = ((const uchar4*)s_cam)[j4];
        int jb = j4 << 2;
        float x0 = (jb     == row) ? INF_F : f.x;
        float x1 = (jb + 1 == row) ? INF_F : f.y;
        float x2 = (jb + 2 == row) ? INF_F : f.z;
        float x3 = (jb + 3 == row) ? INF_F : f.w;
        if (cc.x == mycam) insertN<4>(t4I, x0); else insertN<7>(t7E, x0);
        if (cc.y == mycam) insertN<4>(t4I, x1); else insertN<7>(t7E, x1);
        if (cc.z == mycam) insertN<4>(t4I, x2); else insertN<7>(t7E, x2);
        if (cc.w == mycam) insertN<4>(t4I, x3); else insertN<7>(t7E, x3);
    }

    float mI[4], mEv[7];
    warp_merge<4>(t4I, lane, mI);
    warp_merge<7>(t7E, lane, mEv);
    if (lane == 0) {
        s_lists[wid][0] = mI[0];  s_lists[wid][1] = mI[1];
        s_lists[wid][2] = mI[2];  s_lists[wid][3] = mI[3];
        s_lists[wid][4] = mEv[0]; s_lists[wid][5] = mEv[1];
        s_lists[wid][6] = mEv[2]; s_lists[wid][7] = mEv[3];
        s_lists[wid][8] = mEv[4]; s_lists[wid][9] = mEv[5];
        s_lists[wid][10] = mEv[6];
    }
    __syncthreads();

    // ---- combine halves (each warp computes redundantly; static indices)
    const float* LA = s_lists[rowLocal * 2];
    const float* LB = s_lists[rowLocal * 2 + 1];
    float dKi = merged3(LA, LB);             // real intra rank 3 = combined rank 4
    float dKe = merged6(LA + 4, LB + 4);
    float d0e = fminf(LA[4], LB[4]);

    // ---- pass 2: branchless expf sums over this half
    float si = 0.f, se = 0.f;
#pragma unroll 4
    for (int it = itBeg; it < itEnd; ++it) {
        int j4 = it * 32 + lane;
        float4 f = drow4[j4];
        uchar4 cc = ((const uchar4*)s_cam)[j4];
        int jb = j4 << 2;
        float x0 = (jb     == row) ? INF_F : f.x;
        float x1 = (jb + 1 == row) ? INF_F : f.y;
        float x2 = (jb + 2 == row) ? INF_F : f.z;
        float x3 = (jb + 3 == row) ? INF_F : f.w;
#define ACC1(cm, xx) do { \
        bool m_ = (cm == mycam); \
        float dk_ = m_ ? dKi : dKe; \
        float e_ = __expf(SCALE_F * (dk_ - (xx))); \
        e_ = ((xx) >= dk_) ? e_ : 0.f; \
        if (m_) si += e_; else se += e_; } while (0)
        ACC1(cc.x, x0); ACC1(cc.y, x1); ACC1(cc.z, x2); ACC1(cc.w, x3);
#undef ACC1
    }
#pragma unroll
    for (int off = 16; off; off >>= 1) {
        si += __shfl_xor_sync(0xffffffffu, si, off);
        se += __shfl_xor_sync(0xffffffffu, se, off);
    }
    if (lane == 0) { s_sums[wid][0] = si; s_sums[wid][1] = se; }
    __syncthreads();

    // ---- finalize 4 rows (one thread each)
    if (tid < 4) {
        const float* A = s_lists[tid * 2];
        const float* B = s_lists[tid * 2 + 1];
        float dKi2 = merged3(A, B);
        float dKe2 = merged6(A + 4, B + 4);
        float d0e2 = fminf(A[4], B[4]);
        float Si = s_sums[tid * 2][0] + s_sums[tid * 2 + 1][0];
        float Se = s_sums[tid * 2][1] + s_sums[tid * 2 + 1][1];
        float term_i = 0.f, term_e = 0.f;
        if (isfinite(dKi2))
            term_i = fmaxf(SCALE_F * (sqrtf(EPS_F) - dKi2) + logf(Si) + 40.0f, 0.f);
        if (isfinite(dKe2))
            term_e = fmaxf(SCALE_F * (d0e2 - dKe2) + logf(Se) + 6.0f, 0.f);
        s_part[tid] = term_i + 0.5f * term_e;
    }
    __syncthreads();

    if (tid == 0) {
        float p = s_part[0] + s_part[1] + s_part[2] + s_part[3];
        g_partial[blockIdx.x] = p;
        __threadfence();
        int old = atomicAdd(&g_ctr, 1);
        s_last = (old == nCtas - 1);
    }
    __syncthreads();

    if (s_last) {
        float s = 0.f;
        for (int j = tid; j < nCtas; j += 256) s += g_partial[j];
        s_red[tid] = s;
        __syncthreads();
        for (int st = 128; st; st >>= 1) {
            if (tid < st) s_red[tid] += s_red[tid + st];
            __syncthreads();
        }
        if (tid == 0) { out[0] = s_red[0] / (float)n; g_ctr = 0; }
    }
}

// ===========================================================================
extern "C" void kernel_launch(void* const* d_in, const int* in_sizes, int n_in,
                              void* d_out, int out_size) {
    const float* feat = (const float*)d_in[0];
    const int*   cam  = (const int*)d_in[1];
    int n = in_sizes[1];
    int d = in_sizes[0] / n;
    int NB = n / 128;

    static int smem_set = 0;
    if (!smem_set) {
        cudaFuncSetAttribute(dist_gemm_mma,
                             cudaFuncAttributeMaxDynamicSharedMemorySize,
                             SMEM_GEMM_TOTAL);
        smem_set = 1;
    }

    int rowBlocks = (n + 7) / 8;
    prep_fused_kernel<<<rowBlocks + 1, 256>>>(feat, cam, n, d, rowBlocks);
    dist_gemm_mma<<<NB * (NB + 1) / 2, 256, SMEM_GEMM_TOTAL>>>(n);
    int nCtas = n / 4;
    row_kernel<<<nCtas, 256>>>(n, nCtas, (float*)d_out);
}

// round 14
// speedup vs baseline: 1.2015x; 1.0202x over previous
#include <cuda_runtime.h>
#include <cuda_bf16.h>
#include <math.h>
#include <stdint.h>

#define NMAX 4096
#define DMAX 256
#define KPACK 768              // A pack: [hi|hi|lo]; B = chunk-permutation of A
#define SCALE_F 10.0f
#define EPS_F 1e-5f
#define INF_F __int_as_float(0x7f800000)

__device__ float g_dist[(size_t)NMAX * NMAX];
__device__ float g_sq2[2][NMAX];
__device__ unsigned char g_cam[NMAX];
__device__ float g_partial[NMAX];
__device__ int g_ctr = 0;
__device__ __nv_bfloat16 g_pa[(size_t)NMAX * KPACK];

__device__ __forceinline__ uint32_t smem_to_u32(const void* p) {
    uint32_t a;
    asm("{ .reg .u64 t; cvta.to.shared.u64 t, %1; cvt.u32.u64 %0, t; }"
        : "=r"(a) : "l"(p));
    return a;
}

#define LDMATRIX_X4(R, addr) \
    asm volatile("ldmatrix.sync.aligned.m8n8.x4.shared.b16 {%0,%1,%2,%3}, [%4];" \
        : "=r"((R)[0]), "=r"((R)[1]), "=r"((R)[2]), "=r"((R)[3]) : "r"(addr))
#define MMA_BF16(D, A, B) \
    asm volatile("mma.sync.aligned.m16n8k16.row.col.f32.bf16.bf16.f32 " \
        "{%0,%1,%2,%3}, {%4,%5,%6,%7}, {%8,%9}, {%0,%1,%2,%3};" \
        : "+f"((D)[0]), "+f"((D)[1]), "+f"((D)[2]), "+f"((D)[3]) \
        : "r"((A)[0]), "r"((A)[1]), "r"((A)[2]), "r"((A)[3]), \
          "r"((B)[0]), "r"((B)[1]))
#define CP_ASYNC16(dst, src) \
    asm volatile("cp.async.cg.shared.global [%0], [%1], 16;" \
        :: "r"(dst), "l"(src))
#define CP_COMMIT() asm volatile("cp.async.commit_group;")
#define CP_WAIT(N)  asm volatile("cp.async.wait_group %0;" :: "n"(N))

// ===========================================================================
// Fused prep: TWO warps per row (split+pack+sq halves) | camid normalize
// ===========================================================================
__global__ void prep_fused_kernel(const float* __restrict__ f,
                                  const int* __restrict__ cam_raw,
                                  int n, int d, int rowBlocks) {
    int b = blockIdx.x;
    if (b < rowBlocks) {
        int wid  = threadIdx.x >> 5;
        int lane = threadIdx.x & 31;
        int row  = b * 4 + (wid >> 1);
        int half = wid & 1;
        if (row >= n) return;
        // this warp handles elements [half*128, half*128+128) of the row
        int idx = half * 32 + lane;                       // float4 index in row
        float4 x = ((const float4*)(f + (size_t)row * d))[idx];
        float s = x.x * x.x + x.y * x.y + x.z * x.z + x.w * x.w;
        float xv[4] = {x.x, x.y, x.z, x.w};
        uint32_t hu[2], lu[2];
#pragma unroll
        for (int q = 0; q < 2; ++q) {
            float a = xv[2 * q], c = xv[2 * q + 1];
            __nv_bfloat16 h0 = __float2bfloat16_rn(a);
            __nv_bfloat16 h1 = __float2bfloat16_rn(c);
            __nv_bfloat16 l0 = __float2bfloat16_rn(a - __bfloat162float(h0));
            __nv_bfloat16 l1 = __float2bfloat16_rn(c - __bfloat162float(h1));
            __nv_bfloat162 hh(h0, h1), ll(l0, l1);
            hu[q] = *(uint32_t*)&hh;
            lu[q] = *(uint32_t*)&ll;
        }
#pragma unroll
        for (int off = 16; off; off >>= 1) s += __shfl_down_sync(0xffffffffu, s, off);
        if (lane == 0) g_sq2[half][row] = s;

        uint2 hv = make_uint2(hu[0], hu[1]);
        uint2 lv = make_uint2(lu[0], lu[1]);
        uint2* pa2 = (uint2*)(g_pa + (size_t)row * KPACK);
        pa2[idx] = hv; pa2[64 + idx] = hv; pa2[128 + idx] = lv;
    } else {
        __shared__ int s_is64;
        int tid = threadIdx.x;
        if (tid < 32) {
            int nz = 0;
            if (4 * tid + 3 < 2 * n) {
                uint4 w = ((const uint4*)cam_raw)[tid];
                nz = (w.y != 0) || (w.w != 0);
            }
            unsigned bal = __ballot_sync(0xffffffffu, nz);
            if (tid == 0) { s_is64 = (bal == 0); g_ctr = 0; }
        }
        __syncthreads();
        int is64 = s_is64;
        for (int j = tid; j < n; j += blockDim.x)
            g_cam[j] = (unsigned char)(is64 ? cam_raw[2 * j] : cam_raw[j]);
    }
}

// ===========================================================================
// Distance GEMM via mma.sync bf16, UPPER-TRIANGLE blocks only.
// ===========================================================================
#define NCHUNK (KPACK / 64)
#define BUF_BYTES 32768
#define TLDA 129
#define SMEM_GEMM_TOTAL (1024 + 3 * BUF_BYTES)

__global__ void __launch_bounds__(256, 2) dist_gemm_mma(int n) {
    extern __shared__ char smem_raw[];
    uint32_t sraw = smem_to_u32(smem_raw);
    uint32_t sbase = (sraw + 1023) & ~1023u;
    int tid = threadIdx.x, lane = tid & 31, wid = tid >> 5;

    int NB = n >> 7;
    int t = blockIdx.x;
    int bi = (int)((2.0f * NB + 1.0f -
                    sqrtf((2.0f * NB + 1.0f) * (2.0f * NB + 1.0f) - 8.0f * t)) * 0.5f);
    if (bi < 0) bi = 0;
    if (bi > NB - 1) bi = NB - 1;
#define TRI_START(r) ((r) * NB - ((r) * ((r) - 1)) / 2)
    while (bi + 1 < NB && TRI_START(bi + 1) <= t) ++bi;
    while (bi > 0 && TRI_START(bi) > t) --bi;
    int bj = bi + (t - TRI_START(bi));
#undef TRI_START

    const char* pa = (const char*)(g_pa + (size_t)bi * 128 * KPACK);
    const char* pb = (const char*)(g_pa + (size_t)bj * 128 * KPACK);
    const int ROWB = KPACK * 2;

    int seg = tid & 7, r0 = tid >> 3;

#define LOAD_CHUNK(c, buf) do { \
    int cb_ = ((c) < 4) ? (c) : (((c) < 8) ? (c) + 4 : (c) - 4); \
    uint32_t abase_ = sbase + (buf) * BUF_BYTES; \
    uint32_t bbase_ = abase_ + 16384; \
    _Pragma("unroll") \
    for (int it = 0; it < 4; ++it) { \
        int row = r0 + it * 32; \
        uint32_t off = row * 128 + seg * 16; \
        off = off ^ ((off >> 3) & 0x70); \
        CP_ASYNC16(abase_ + off, pa + (size_t)row * ROWB + (c) * 128 + seg * 16); \
        CP_ASYNC16(bbase_ + off, pb + (size_t)row * ROWB + cb_ * 128 + seg * 16); \
    } \
    CP_COMMIT(); \
} while (0)

    int wr = wid >> 2, wc = wid & 3;
    int wm = wr * 64, wn = wc * 32;

    float acc[4][4][4];
#pragma unroll
    for (int mt = 0; mt < 4; ++mt)
#pragma unroll
        for (int nt = 0; nt < 4; ++nt)
#pragma unroll
            for (int e = 0; e < 4; ++e) acc[mt][nt][e] = 0.f;

    LOAD_CHUNK(0, 0);
    LOAD_CHUNK(1, 1);
    for (int c = 0; c < NCHUNK; ++c) {
        if (c == NCHUNK - 1) CP_WAIT(0);
        else                 CP_WAIT(1);
        __syncthreads();
        if (c + 2 < NCHUNK) LOAD_CHUNK(c + 2, (c + 2) % 3);

        uint32_t abase = sbase + (c % 3) * BUF_BYTES;
        uint32_t bbase = abase + 16384;
#pragma unroll
        for (int kk = 0; kk < 4; ++kk) {
            uint32_t afr[4][4], bfr[4][2];
#pragma unroll
            for (int mt = 0; mt < 4; ++mt) {
                int row = wm + mt * 16 + (lane & 15);
                uint32_t off = row * 128 + kk * 32 + (lane >> 4) * 16;
                off = off ^ ((off >> 3) & 0x70);
                LDMATRIX_X4(afr[mt], abase + off);
            }
#pragma unroll
            for (int np = 0; np < 2; ++np) {
                int row = wn + np * 16 + ((lane >> 4) << 3) + (lane & 7);
                uint32_t off = row * 128 + kk * 32 + (((lane >> 3) & 1) << 4);
                off = off ^ ((off >> 3) & 0x70);
                uint32_t q[4];
                LDMATRIX_X4(q, bbase + off);
                bfr[np * 2 + 0][0] = q[0]; bfr[np * 2 + 0][1] = q[1];
                bfr[np * 2 + 1][0] = q[2]; bfr[np * 2 + 1][1] = q[3];
            }
#pragma unroll
            for (int mt = 0; mt < 4; ++mt)
#pragma unroll
                for (int nt = 0; nt < 4; ++nt)
                    MMA_BF16(acc[mt][nt], afr[mt], bfr[nt]);
        }
    }

    __shared__ float ssq[256];
    float* s_tile = (float*)(smem_raw + (sbase - sraw));
    if (tid < 128) ssq[tid] = g_sq2[0][bi * 128 + tid] + g_sq2[1][bi * 128 + tid];
    else ssq[tid] = g_sq2[0][bj * 128 + (tid - 128)] + g_sq2[1][bj * 128 + (tid - 128)];
    __syncthreads();

    int g4 = lane >> 2, t4 = lane & 3;
#pragma unroll
    for (int mt = 0; mt < 4; ++mt) {
#pragma unroll
        for (int half = 0; half < 2; ++half) {
            int r = wm + mt * 16 + g4 + half * 8;
            int gi = bi * 128 + r;
            float sqi = ssq[r];
#pragma unroll
            for (int nt = 0; nt < 4; ++nt) {
                int col = wn + nt * 8 + 2 * t4;
                int gj = bj * 128 + col;
                float2 o;
                float d0 = sqi + ssq[128 + col] + EPS_F
                           - 2.0f * acc[mt][nt][half * 2 + 0];
                float d1 = sqi + ssq[128 + col + 1] + EPS_F
                           - 2.0f * acc[mt][nt][half * 2 + 1];
                o.x = sqrtf(fmaxf(d0, 1e-12f));
                o.y = sqrtf(fmaxf(d1, 1e-12f));
                if (gi == gj)     o.x = sqrtf(EPS_F);
                if (gi == gj + 1) o.y = sqrtf(EPS_F);
                *(float2*)(g_dist + (size_t)gi * n + gj) = o;
                s_tile[r * TLDA + col]     = o.x;
                s_tile[r * TLDA + col + 1] = o.y;
            }
        }
    }

    if (bi != bj) {
        __syncthreads();
#pragma unroll
        for (int it = 0; it < 16; ++it) {
            int c = it * 8 + wid;
            float* orow = g_dist + (size_t)(bj * 128 + c) * n + bi * 128;
#pragma unroll
            for (int q = 0; q < 4; ++q) {
                int r = lane + q * 32;
                orow[r] = s_tile[r * TLDA + c];
            }
        }
    }
#undef LOAD_CHUNK
}

// ===========================================================================
// Row kernel v6: two warps per row + EXPLICIT 4-deep load batching (MLP=4)
// in both passes. Halves combined via closed-form order statistics.
// ===========================================================================
template <int N>
__device__ __forceinline__ void insertN(float (&t)[N], float x) {
    if (x < t[N - 1]) {
        t[N - 1] = x;
#pragma unroll
        for (int k = N - 1; k > 0; --k) {
            float a = t[k - 1], b = t[k];
            t[k - 1] = fminf(a, b); t[k] = fmaxf(a, b);
        }
    }
}

template <int N>
__device__ __forceinline__ void warp_merge(float (&t)[N], int lane, float (&out)[N]) {
#pragma unroll
    for (int r = 0; r < N; ++r) {
        float bv = t[0]; int bl = lane;
#pragma unroll
        for (int off = 16; off; off >>= 1) {
            float ov = __shfl_down_sync(0xffffffffu, bv, off);
            int   ol = __shfl_down_sync(0xffffffffu, bl, off);
            if (ov < bv) { bv = ov; bl = ol; }
        }
        bv = __shfl_sync(0xffffffffu, bv, 0);
        bl = __shfl_sync(0xffffffffu, bl, 0);
        if (lane == bl) {
#pragma unroll
            for (int k = 0; k < N - 1; ++k) t[k] = t[k + 1];
            t[N - 1] = INF_F;
        }
        out[r] = bv;
    }
}

__device__ __forceinline__ float merged3(const float* A, const float* B) {
    float m = B[3];
    m = fminf(m, fmaxf(A[0], B[2]));
    m = fminf(m, fmaxf(A[1], B[1]));
    m = fminf(m, fmaxf(A[2], B[0]));
    m = fminf(m, A[3]);
    return m;
}
__device__ __forceinline__ float merged6(const float* A, const float* B) {
    float m = B[6];
    m = fminf(m, fmaxf(A[0], B[5]));
    m = fminf(m, fmaxf(A[1], B[4]));
    m = fminf(m, fmaxf(A[2], B[3]));
    m = fminf(m, fmaxf(A[3], B[2]));
    m = fminf(m, fmaxf(A[4], B[1]));
    m = fminf(m, fmaxf(A[5], B[0]));
    m = fminf(m, A[6]);
    return m;
}

__global__ void __launch_bounds__(256) row_kernel(int n, int nCtas,
                                                  float* __restrict__ out) {
    __shared__ unsigned char s_cam[NMAX];
    __shared__ float s_lists[8][12];
    __shared__ float s_sums[8][2];
    __shared__ float s_part[4];
    __shared__ float s_red[256];
    __shared__ int   s_last;

    int tid = threadIdx.x, wid = tid >> 5, lane = tid & 31;
    int rowLocal = wid >> 1, half = wid & 1;
    int row = blockIdx.x * 4 + rowLocal;

    for (int j = tid; j < n / 16; j += 256)
        ((uint4*)s_cam)[j] = ((const uint4*)g_cam)[j];
    __syncthreads();

    int mycam = s_cam[row];
    const float4* drow4 = (const float4*)(g_dist + (size_t)row * n);
    int itBeg = half * 16;

    // ---- pass 1: guarded inserts, 4 loads in flight per group
    float t4I[4], t7E[7];
#pragma unroll
    for (int k = 0; k < 4; ++k) t4I[k] = INF_F;
#pragma unroll
    for (int k = 0; k < 7; ++k) t7E[k] = INF_F;

    for (int base = itBeg; base < itBeg + 16; base += 4) {
        float4 f[4]; uchar4 c[4];
#pragma unroll
        for (int q = 0; q < 4; ++q) {
            int j4 = (base + q) * 32 + lane;
            f[q] = drow4[j4];
            c[q] = ((const uchar4*)s_cam)[j4];
        }
#pragma unroll
        for (int q = 0; q < 4; ++q) {
            int jb = ((base + q) * 32 + lane) << 2;
            float x0 = (jb     == row) ? INF_F : f[q].x;
            float x1 = (jb + 1 == row) ? INF_F : f[q].y;
            float x2 = (jb + 2 == row) ? INF_F : f[q].z;
            float x3 = (jb + 3 == row) ? INF_F : f[q].w;
            if (c[q].x == mycam) insertN<4>(t4I, x0); else insertN<7>(t7E, x0);
            if (c[q].y == mycam) insertN<4>(t4I, x1); else insertN<7>(t7E, x1);
            if (c[q].z == mycam) insertN<4>(t4I, x2); else insertN<7>(t7E, x2);
            if (c[q].w == mycam) insertN<4>(t4I, x3); else insertN<7>(t7E, x3);
        }
    }

    float mI[4], mEv[7];
    warp_merge<4>(t4I, lane, mI);
    warp_merge<7>(t7E, lane, mEv);
    if (lane == 0) {
        s_lists[wid][0] = mI[0];  s_lists[wid][1] = mI[1];
        s_lists[wid][2] = mI[2];  s_lists[wid][3] = mI[3];
        s_lists[wid][4] = mEv[0]; s_lists[wid][5] = mEv[1];
        s_lists[wid][6] = mEv[2]; s_lists[wid][7] = mEv[3];
        s_lists[wid][8] = mEv[4]; s_lists[wid][9] = mEv[5];
        s_lists[wid][10] = mEv[6];
    }
    __syncthreads();

    const float* LA = s_lists[rowLocal * 2];
    const float* LB = s_lists[rowLocal * 2 + 1];
    float dKi = merged3(LA, LB);
    float dKe = merged6(LA + 4, LB + 4);

    // ---- pass 2: branchless expf sums, 4 loads in flight (L2-hot)
    float si = 0.f, se = 0.f;
    for (int base = itBeg; base < itBeg + 16; base += 4) {
        float4 f[4]; uchar4 c[4];
#pragma unroll
        for (int q = 0; q < 4; ++q) {
            int j4 = (base + q) * 32 + lane;
            f[q] = drow4[j4];
            c[q] = ((const uchar4*)s_cam)[j4];
        }
#pragma unroll
        for (int q = 0; q < 4; ++q) {
            int jb = ((base + q) * 32 + lane) << 2;
            float x0 = (jb     == row) ? INF_F : f[q].x;
            float x1 = (jb + 1 == row) ? INF_F : f[q].y;
            float x2 = (jb + 2 == row) ? INF_F : f[q].z;
            float x3 = (jb + 3 == row) ? INF_F : f[q].w;
#define ACC1(cm, xx) do { \
            bool m_ = (cm == mycam); \
            float dk_ = m_ ? dKi : dKe; \
            float e_ = __expf(SCALE_F * (dk_ - (xx))); \
            e_ = ((xx) >= dk_) ? e_ : 0.f; \
            if (m_) si += e_; else se += e_; } while (0)
            ACC1(c[q].x, x0); ACC1(c[q].y, x1); ACC1(c[q].z, x2); ACC1(c[q].w, x3);
#undef ACC1
        }
    }
#pragma unroll
    for (int off = 16; off; off >>= 1) {
        si += __shfl_xor_sync(0xffffffffu, si, off);
        se += __shfl_xor_sync(0xffffffffu, se, off);
    }
    if (lane == 0) { s_sums[wid][0] = si; s_sums[wid][1] = se; }
    __syncthreads();

    if (tid < 4) {
        const float* A = s_lists[tid * 2];
        const float* B = s_lists[tid * 2 + 1];
        float dKi2 = merged3(A, B);
        float dKe2 = merged6(A + 4, B + 4);
        float d0e2 = fminf(A[4], B[4]);
        float Si = s_sums[tid * 2][0] + s_sums[tid * 2 + 1][0];
        float Se = s_sums[tid * 2][1] + s_sums[tid * 2 + 1][1];
        float term_i = 0.f, term_e = 0.f;
        if (isfinite(dKi2))
            term_i = fmaxf(SCALE_F * (sqrtf(EPS_F) - dKi2) + logf(Si) + 40.0f, 0.f);
        if (isfinite(dKe2))
            term_e = fmaxf(SCALE_F * (d0e2 - dKe2) + logf(Se) + 6.0f, 0.f);
        s_part[tid] = term_i + 0.5f * term_e;
    }
    __syncthreads();

    if (tid == 0) {
        float p = s_part[0] + s_part[1] + s_part[2] + s_part[3];
        g_partial[blockIdx.x] = p;
        __threadfence();
        int old = atomicAdd(&g_ctr, 1);
        s_last = (old == nCtas - 1);
    }
    __syncthreads();

    if (s_last) {
        float s = 0.f;
        for (int j = tid; j < nCtas; j += 256) s += g_partial[j];
        s_red[tid] = s;
        __syncthreads();
        for (int st = 128; st; st >>= 1) {
            if (tid < st) s_red[tid] += s_red[tid + st];
            __syncthreads();
        }
        if (tid == 0) { out[0] = s_red[0] / (float)n; g_ctr = 0; }
    }
}

// ===========================================================================
extern "C" void kernel_launch(void* const* d_in, const int* in_sizes, int n_in,
                              void* d_out, int out_size) {
    const float* feat = (const float*)d_in[0];
    const int*   cam  = (const int*)d_in[1];
    int n = in_sizes[1];
    int d = in_sizes[0] / n;
    int NB = n / 128;

    static int smem_set = 0;
    if (!smem_set) {
        cudaFuncSetAttribute(dist_gemm_mma,
                             cudaFuncAttributeMaxDynamicSharedMemorySize,
                             SMEM_GEMM_TOTAL);
        smem_set = 1;
    }

    int rowBlocks = (n + 3) / 4;    // 2 warps/row, 4 rows per 256-thread block
    prep_fused_kernel<<<rowBlocks + 1, 256>>>(feat, cam, n, d, rowBlocks);
    dist_gemm_mma<<<NB * (NB + 1) / 2, 256, SMEM_GEMM_TOTAL>>>(n);
    int nCtas = n / 4;
    row_kernel<<<nCtas, 256>>>(n, nCtas, (float*)d_out);
}

// round 15
// speedup vs baseline: 1.3596x; 1.1316x over previous
#include <cuda_runtime.h>
#include <cuda_bf16.h>
#include <math.h>
#include <stdint.h>

#define NMAX 4096
#define DMAX 256
#define KPACK 512              // A pack: [hi|lo]; B = [hi|hi] via chunk remap
#define SCALE_F 10.0f
#define EPS_F 1e-5f
#define INF_F __int_as_float(0x7f800000)

__device__ float g_dist[(size_t)NMAX * NMAX];
__device__ float g_sq2[2][NMAX];
__device__ unsigned char g_cam[NMAX];
__device__ float g_partial[NMAX];
__device__ int g_ctr = 0;
__device__ __nv_bfloat16 g_pa[(size_t)NMAX * KPACK];

__device__ __forceinline__ uint32_t smem_to_u32(const void* p) {
    uint32_t a;
    asm("{ .reg .u64 t; cvta.to.shared.u64 t, %1; cvt.u32.u64 %0, t; }"
        : "=r"(a) : "l"(p));
    return a;
}

#define LDMATRIX_X4(R, addr) \
    asm volatile("ldmatrix.sync.aligned.m8n8.x4.shared.b16 {%0,%1,%2,%3}, [%4];" \
        : "=r"((R)[0]), "=r"((R)[1]), "=r"((R)[2]), "=r"((R)[3]) : "r"(addr))
#define MMA_BF16(D, A, B) \
    asm volatile("mma.sync.aligned.m16n8k16.row.col.f32.bf16.bf16.f32 " \
        "{%0,%1,%2,%3}, {%4,%5,%6,%7}, {%8,%9}, {%0,%1,%2,%3};" \
        : "+f"((D)[0]), "+f"((D)[1]), "+f"((D)[2]), "+f"((D)[3]) \
        : "r"((A)[0]), "r"((A)[1]), "r"((A)[2]), "r"((A)[3]), \
          "r"((B)[0]), "r"((B)[1]))
#define CP_ASYNC16(dst, src) \
    asm volatile("cp.async.cg.shared.global [%0], [%1], 16;" \
        :: "r"(dst), "l"(src))
#define CP_COMMIT() asm volatile("cp.async.commit_group;")
#define CP_WAIT(N)  asm volatile("cp.async.wait_group %0;" :: "n"(N))

// ===========================================================================
// Fused prep: TWO warps per row (split+pack+sq halves) | camid normalize
// ===========================================================================
__global__ void prep_fused_kernel(const float* __restrict__ f,
                                  const int* __restrict__ cam_raw,
                                  int n, int d, int rowBlocks) {
    int b = blockIdx.x;
    if (b < rowBlocks) {
        int wid  = threadIdx.x >> 5;
        int lane = threadIdx.x & 31;
        int row  = b * 4 + (wid >> 1);
        int half = wid & 1;
        if (row >= n) return;
        int idx = half * 32 + lane;                       // float4 index in row
        float4 x = ((const float4*)(f + (size_t)row * d))[idx];
        float s = x.x * x.x + x.y * x.y + x.z * x.z + x.w * x.w;
        float xv[4] = {x.x, x.y, x.z, x.w};
        uint32_t hu[2], lu[2];
#pragma unroll
        for (int q = 0; q < 2; ++q) {
            float a = xv[2 * q], c = xv[2 * q + 1];
            __nv_bfloat16 h0 = __float2bfloat16_rn(a);
            __nv_bfloat16 h1 = __float2bfloat16_rn(c);
            __nv_bfloat16 l0 = __float2bfloat16_rn(a - __bfloat162float(h0));
            __nv_bfloat16 l1 = __float2bfloat16_rn(c - __bfloat162float(h1));
            __nv_bfloat162 hh(h0, h1), ll(l0, l1);
            hu[q] = *(uint32_t*)&hh;
            lu[q] = *(uint32_t*)&ll;
        }
#pragma unroll
        for (int off = 16; off; off >>= 1) s += __shfl_down_sync(0xffffffffu, s, off);
        if (lane == 0) g_sq2[half][row] = s;

        uint2 hv = make_uint2(hu[0], hu[1]);
        uint2 lv = make_uint2(lu[0], lu[1]);
        uint2* pa2 = (uint2*)(g_pa + (size_t)row * KPACK);
        pa2[idx] = hv; pa2[64 + idx] = lv;     // [hi(64 uint2) | lo(64 uint2)]
    } else {
        __shared__ int s_is64;
        int tid = threadIdx.x;
        if (tid < 32) {
            int nz = 0;
            if (4 * tid + 3 < 2 * n) {
                uint4 w = ((const uint4*)cam_raw)[tid];
                nz = (w.y != 0) || (w.w != 0);
            }
            unsigned bal = __ballot_sync(0xffffffffu, nz);
            if (tid == 0) { s_is64 = (bal == 0); g_ctr = 0; }
        }
        __syncthreads();
        int is64 = s_is64;
        for (int j = tid; j < n; j += blockDim.x)
            g_cam[j] = (unsigned char)(is64 ? cam_raw[2 * j] : cam_raw[j]);
    }
}

// ===========================================================================
// Distance GEMM via mma.sync bf16, UPPER-TRIANGLE blocks only.
// A reads chunks 0..7 of [hi|lo]; B remaps: c<4 -> hi chunk c, c>=4 -> hi
// chunk c-4 (i.e. B = [hi|hi]). Product = hi.hi + lo.hi (symmetric).
// ===========================================================================
#define NCHUNK (KPACK / 64)          // 8
#define BUF_BYTES 32768
#define TLDA 129
#define SMEM_GEMM_TOTAL (1024 + 3 * BUF_BYTES)

__global__ void __launch_bounds__(256, 2) dist_gemm_mma(int n) {
    extern __shared__ char smem_raw[];
    uint32_t sraw = smem_to_u32(smem_raw);
    uint32_t sbase = (sraw + 1023) & ~1023u;
    int tid = threadIdx.x, lane = tid & 31, wid = tid >> 5;

    int NB = n >> 7;
    int t = blockIdx.x;
    int bi = (int)((2.0f * NB + 1.0f -
                    sqrtf((2.0f * NB + 1.0f) * (2.0f * NB + 1.0f) - 8.0f * t)) * 0.5f);
    if (bi < 0) bi = 0;
    if (bi > NB - 1) bi = NB - 1;
#define TRI_START(r) ((r) * NB - ((r) * ((r) - 1)) / 2)
    while (bi + 1 < NB && TRI_START(bi + 1) <= t) ++bi;
    while (bi > 0 && TRI_START(bi) > t) --bi;
    int bj = bi + (t - TRI_START(bi));
#undef TRI_START

    const char* pa = (const char*)(g_pa + (size_t)bi * 128 * KPACK);
    const char* pb = (const char*)(g_pa + (size_t)bj * 128 * KPACK);
    const int ROWB = KPACK * 2;      // 1024 bytes per row

    int seg = tid & 7, r0 = tid >> 3;

#define LOAD_CHUNK(c, buf) do { \
    int cb_ = ((c) < 4) ? (c) : (c) - 4; \
    uint32_t abase_ = sbase + (buf) * BUF_BYTES; \
    uint32_t bbase_ = abase_ + 16384; \
    _Pragma("unroll") \
    for (int it = 0; it < 4; ++it) { \
        int row = r0 + it * 32; \
        uint32_t off = row * 128 + seg * 16; \
        off = off ^ ((off >> 3) & 0x70); \
        CP_ASYNC16(abase_ + off, pa + (size_t)row * ROWB + (c) * 128 + seg * 16); \
        CP_ASYNC16(bbase_ + off, pb + (size_t)row * ROWB + cb_ * 128 + seg * 16); \
    } \
    CP_COMMIT(); \
} while (0)

    int wr = wid >> 2, wc = wid & 3;
    int wm = wr * 64, wn = wc * 32;

    float acc[4][4][4];
#pragma unroll
    for (int mt = 0; mt < 4; ++mt)
#pragma unroll
        for (int nt = 0; nt < 4; ++nt)
#pragma unroll
            for (int e = 0; e < 4; ++e) acc[mt][nt][e] = 0.f;

    LOAD_CHUNK(0, 0);
    LOAD_CHUNK(1, 1);
    for (int c = 0; c < NCHUNK; ++c) {
        if (c == NCHUNK - 1) CP_WAIT(0);
        else                 CP_WAIT(1);
        __syncthreads();
        if (c + 2 < NCHUNK) LOAD_CHUNK(c + 2, (c + 2) % 3);

        uint32_t abase = sbase + (c % 3) * BUF_BYTES;
        uint32_t bbase = abase + 16384;
#pragma unroll
        for (int kk = 0; kk < 4; ++kk) {
            uint32_t afr[4][4], bfr[4][2];
#pragma unroll
            for (int mt = 0; mt < 4; ++mt) {
                int row = wm + mt * 16 + (lane & 15);
                uint32_t off = row * 128 + kk * 32 + (lane >> 4) * 16;
                off = off ^ ((off >> 3) & 0x70);
                LDMATRIX_X4(afr[mt], abase + off);
            }
#pragma unroll
            for (int np = 0; np < 2; ++np) {
                int row = wn + np * 16 + ((lane >> 4) << 3) + (lane & 7);
                uint32_t off = row * 128 + kk * 32 + (((lane >> 3) & 1) << 4);
                off = off ^ ((off >> 3) & 0x70);
                uint32_t q[4];
                LDMATRIX_X4(q, bbase + off);
                bfr[np * 2 + 0][0] = q[0]; bfr[np * 2 + 0][1] = q[1];
                bfr[np * 2 + 1][0] = q[2]; bfr[np * 2 + 1][1] = q[3];
            }
#pragma unroll
            for (int mt = 0; mt < 4; ++mt)
#pragma unroll
                for (int nt = 0; nt < 4; ++nt)
                    MMA_BF16(acc[mt][nt], afr[mt], bfr[nt]);
        }
    }

    __shared__ float ssq[256];
    float* s_tile = (float*)(smem_raw + (sbase - sraw));
    if (tid < 128) ssq[tid] = g_sq2[0][bi * 128 + tid] + g_sq2[1][bi * 128 + tid];
    else ssq[tid] = g_sq2[0][bj * 128 + (tid - 128)] + g_sq2[1][bj * 128 + (tid - 128)];
    __syncthreads();

    int g4 = lane >> 2, t4 = lane & 3;
#pragma unroll
    for (int mt = 0; mt < 4; ++mt) {
#pragma unroll
        for (int half = 0; half < 2; ++half) {
            int r = wm + mt * 16 + g4 + half * 8;
            int gi = bi * 128 + r;
            float sqi = ssq[r];
#pragma unroll
            for (int nt = 0; nt < 4; ++nt) {
                int col = wn + nt * 8 + 2 * t4;
                int gj = bj * 128 + col;
                float2 o;
                float d0 = sqi + ssq[128 + col] + EPS_F
                           - 2.0f * acc[mt][nt][half * 2 + 0];
                float d1 = sqi + ssq[128 + col + 1] + EPS_F
                           - 2.0f * acc[mt][nt][half * 2 + 1];
                o.x = sqrtf(fmaxf(d0, 1e-12f));
                o.y = sqrtf(fmaxf(d1, 1e-12f));
                if (gi == gj)     o.x = sqrtf(EPS_F);
                if (gi == gj + 1) o.y = sqrtf(EPS_F);
                *(float2*)(g_dist + (size_t)gi * n + gj) = o;
                s_tile[r * TLDA + col]     = o.x;
                s_tile[r * TLDA + col + 1] = o.y;
            }
        }
    }

    if (bi != bj) {
        __syncthreads();
#pragma unroll
        for (int it = 0; it < 16; ++it) {
            int c = it * 8 + wid;
            float* orow = g_dist + (size_t)(bj * 128 + c) * n + bi * 128;
#pragma unroll
            for (int q = 0; q < 4; ++q) {
                int r = lane + q * 32;
                orow[r] = s_tile[r * TLDA + c];
            }
        }
    }
#undef LOAD_CHUNK
}

// ===========================================================================
// Row kernel v6 (R14): two warps per row + explicit MLP=4 batching.
// ===========================================================================
template <int N>
__device__ __forceinline__ void insertN(float (&t)[N], float x) {
    if (x < t[N - 1]) {
        t[N - 1] = x;
#pragma unroll
        for (int k = N - 1; k > 0; --k) {
            float a = t[k - 1], b = t[k];
            t[k - 1] = fminf(a, b); t[k] = fmaxf(a, b);
        }
    }
}

template <int N>
__device__ __forceinline__ void warp_merge(float (&t)[N], int lane, float (&out)[N]) {
#pragma unroll
    for (int r = 0; r < N; ++r) {
        float bv = t[0]; int bl = lane;
#pragma unroll
        for (int off = 16; off; off >>= 1) {
            float ov = __shfl_down_sync(0xffffffffu, bv, off);
            int   ol = __shfl_down_sync(0xffffffffu, bl, off);
            if (ov < bv) { bv = ov; bl = ol; }
        }
        bv = __shfl_sync(0xffffffffu, bv, 0);
        bl = __shfl_sync(0xffffffffu, bl, 0);
        if (lane == bl) {
#pragma unroll
            for (int k = 0; k < N - 1; ++k) t[k] = t[k + 1];
            t[N - 1] = INF_F;
        }
        out[r] = bv;
    }
}

__device__ __forceinline__ float merged3(const float* A, const float* B) {
    float m = B[3];
    m = fminf(m, fmaxf(A[0], B[2]));
    m = fminf(m, fmaxf(A[1], B[1]));
    m = fminf(m, fmaxf(A[2], B[0]));
    m = fminf(m, A[3]);
    return m;
}
__device__ __forceinline__ float merged6(const float* A, const float* B) {
    float m = B[6];
    m = fminf(m, fmaxf(A[0], B[5]));
    m = fminf(m, fmaxf(A[1], B[4]));
    m = fminf(m, fmaxf(A[2], B[3]));
    m = fminf(m, fmaxf(A[3], B[2]));
    m = fminf(m, fmaxf(A[4], B[1]));
    m = fminf(m, fmaxf(A[5], B[0]));
    m = fminf(m, A[6]);
    return m;
}

__global__ void __launch_bounds__(256) row_kernel(int n, int nCtas,
                                                  float* __restrict__ out) {
    __shared__ unsigned char s_cam[NMAX];
    __shared__ float s_lists[8][12];
    __shared__ float s_sums[8][2];
    __shared__ float s_part[4];
    __shared__ float s_red[256];
    __shared__ int   s_last;

    int tid = threadIdx.x, wid = tid >> 5, lane = tid & 31;
    int rowLocal = wid >> 1, half = wid & 1;
    int row = blockIdx.x * 4 + rowLocal;

    for (int j = tid; j < n / 16; j += 256)
        ((uint4*)s_cam)[j] = ((const uint4*)g_cam)[j];
    __syncthreads();

    int mycam = s_cam[row];
    const float4* drow4 = (const float4*)(g_dist + (size_t)row * n);
    int itBeg = half * 16;

    float t4I[4], t7E[7];
#pragma unroll
    for (int k = 0; k < 4; ++k) t4I[k] = INF_F;
#pragma unroll
    for (int k = 0; k < 7; ++k) t7E[k] = INF_F;

    for (int base = itBeg; base < itBeg + 16; base += 4) {
        float4 f[4]; uchar4 c[4];
#pragma unroll
        for (int q = 0; q < 4; ++q) {
            int j4 = (base + q) * 32 + lane;
            f[q] = drow4[j4];
            c[q] = ((const uchar4*)s_cam)[j4];
        }
#pragma unroll
        for (int q = 0; q < 4; ++q) {
            int jb = ((base + q) * 32 + lane) << 2;
            float x0 = (jb     == row) ? INF_F : f[q].x;
            float x1 = (jb + 1 == row) ? INF_F : f[q].y;
            float x2 = (jb + 2 == row) ? INF_F : f[q].z;
            float x3 = (jb + 3 == row) ? INF_F : f[q].w;
            if (c[q].x == mycam) insertN<4>(t4I, x0); else insertN<7>(t7E, x0);
            if (c[q].y == mycam) insertN<4>(t4I, x1); else insertN<7>(t7E, x1);
            if (c[q].z == mycam) insertN<4>(t4I, x2); else insertN<7>(t7E, x2);
            if (c[q].w == mycam) insertN<4>(t4I, x3); else insertN<7>(t7E, x3);
        }
    }

    float mI[4], mEv[7];
    warp_merge<4>(t4I, lane, mI);
    warp_merge<7>(t7E, lane, mEv);
    if (lane == 0) {
        s_lists[wid][0] = mI[0];  s_lists[wid][1] = mI[1];
        s_lists[wid][2] = mI[2];  s_lists[wid][3] = mI[3];
        s_lists[wid][4] = mEv[0]; s_lists[wid][5] = mEv[1];
        s_lists[wid][6] = mEv[2]; s_lists[wid][7] = mEv[3];
        s_lists[wid][8] = mEv[4]; s_lists[wid][9] = mEv[5];
        s_lists[wid][10] = mEv[6];
    }
    __syncthreads();

    const float* LA = s_lists[rowLocal * 2];
    const float* LB = s_lists[rowLocal * 2 + 1];
    float dKi = merged3(LA, LB);
    float dKe = merged6(LA + 4, LB + 4);

    float si = 0.f, se = 0.f;
    for (int base = itBeg; base < itBeg + 16; base += 4) {
        float4 f[4]; uchar4 c[4];
#pragma unroll
        for (int q = 0; q < 4; ++q) {
            int j4 = (base + q) * 32 + lane;
            f[q] = drow4[j4];
            c[q] = ((const uchar4*)s_cam)[j4];
        }
#pragma unroll
        for (int q = 0; q < 4; ++q) {
            int jb = ((base + q) * 32 + lane) << 2;
            float x0 = (jb     == row) ? INF_F : f[q].x;
            float x1 = (jb + 1 == row) ? INF_F : f[q].y;
            float x2 = (jb + 2 == row) ? INF_F : f[q].z;
            float x3 = (jb + 3 == row) ? INF_F : f[q].w;
#define ACC1(cm, xx) do { \
            bool m_ = (cm == mycam); \
            float dk_ = m_ ? dKi : dKe; \
            float e_ = __expf(SCALE_F * (dk_ - (xx))); \
            e_ = ((xx) >= dk_) ? e_ : 0.f; \
            if (m_) si += e_; else se += e_; } while (0)
            ACC1(c[q].x, x0); ACC1(c[q].y, x1); ACC1(c[q].z, x2); ACC1(c[q].w, x3);
#undef ACC1
        }
    }
#pragma unroll
    for (int off = 16; off; off >>= 1) {
        si += __shfl_xor_sync(0xffffffffu, si, off);
        se += __shfl_xor_sync(0xffffffffu, se, off);
    }
    if (lane == 0) { s_sums[wid][0] = si; s_sums[wid][1] = se; }
    __syncthreads();

    if (tid < 4) {
        const float* A = s_lists[tid * 2];
        const float* B = s_lists[tid * 2 + 1];
        float dKi2 = merged3(A, B);
        float dKe2 = merged6(A + 4, B + 4);
        float d0e2 = fminf(A[4], B[4]);
        float Si = s_sums[tid * 2][0] + s_sums[tid * 2 + 1][0];
        float Se = s_sums[tid * 2][1] + s_sums[tid * 2 + 1][1];
        float term_i = 0.f, term_e = 0.f;
        if (isfinite(dKi2))
            term_i = fmaxf(SCALE_F * (sqrtf(EPS_F) - dKi2) + logf(Si) + 40.0f, 0.f);
        if (isfinite(dKe2))
            term_e = fmaxf(SCALE_F * (d0e2 - dKe2) + logf(Se) + 6.0f, 0.f);
        s_part[tid] = term_i + 0.5f * term_e;
    }
    __syncthreads();

    if (tid == 0) {
        float p = s_part[0] + s_part[1] + s_part[2] + s_part[3];
        g_partial[blockIdx.x] = p;
        __threadfence();
        int old = atomicAdd(&g_ctr, 1);
        s_last = (old == nCtas - 1);
    }
    __syncthreads();

    if (s_last) {
        float s = 0.f;
        for (int j = tid; j < nCtas; j += 256) s += g_partial[j];
        s_red[tid] = s;
        __syncthreads();
        for (int st = 128; st; st >>= 1) {
            if (tid < st) s_red[tid] += s_red[tid + st];
            __syncthreads();
        }
        if (tid == 0) { out[0] = s_red[0] / (float)n; g_ctr = 0; }
    }
}

// ===========================================================================
extern "C" void kernel_launch(void* const* d_in, const int* in_sizes, int n_in,
                              void* d_out, int out_size) {
    const float* feat = (const float*)d_in[0];
    const int*   cam  = (const int*)d_in[1];
    int n = in_sizes[1];
    int d = in_sizes[0] / n;
    int NB = n / 128;

    static int smem_set = 0;
    if (!smem_set) {
        cudaFuncSetAttribute(dist_gemm_mma,
                             cudaFuncAttributeMaxDynamicSharedMemorySize,
                             SMEM_GEMM_TOTAL);
        smem_set = 1;
    }

    int rowBlocks = (n + 3) / 4;
    prep_fused_kernel<<<rowBlocks + 1, 256>>>(feat, cam, n, d, rowBlocks);
    dist_gemm_mma<<<NB * (NB + 1) / 2, 256, SMEM_GEMM_TOTAL>>>(n);
    int nCtas = n / 4;
    row_kernel<<<nCtas, 256>>>(n, nCtas, (float*)d_out);
}

// round 16
// speedup vs baseline: 1.4954x; 1.0998x over previous
#include <cuda_runtime.h>
#include <cuda_bf16.h>
#include <math.h>
#include <stdint.h>

#define NMAX 4096
#define DMAX 256
#define KPACK 256              // pure hi pack; A = B (exact symmetry)
#define SCALE_F 10.0f
#define EPS_F 1e-5f
#define INF_F __int_as_float(0x7f800000)

__device__ float g_dist[(size_t)NMAX * NMAX];
__device__ float g_sq2[2][NMAX];
__device__ unsigned char g_cam[NMAX];
__device__ float g_partial[NMAX];
__device__ int g_ctr = 0;
__device__ __nv_bfloat16 g_pa[(size_t)NMAX * KPACK];

__device__ __forceinline__ uint32_t smem_to_u32(const void* p) {
    uint32_t a;
    asm("{ .reg .u64 t; cvta.to.shared.u64 t, %1; cvt.u32.u64 %0, t; }"
        : "=r"(a) : "l"(p));
    return a;
}

#define LDMATRIX_X4(R, addr) \
    asm volatile("ldmatrix.sync.aligned.m8n8.x4.shared.b16 {%0,%1,%2,%3}, [%4];" \
        : "=r"((R)[0]), "=r"((R)[1]), "=r"((R)[2]), "=r"((R)[3]) : "r"(addr))
#define MMA_BF16(D, A, B) \
    asm volatile("mma.sync.aligned.m16n8k16.row.col.f32.bf16.bf16.f32 " \
        "{%0,%1,%2,%3}, {%4,%5,%6,%7}, {%8,%9}, {%0,%1,%2,%3};" \
        : "+f"((D)[0]), "+f"((D)[1]), "+f"((D)[2]), "+f"((D)[3]) \
        : "r"((A)[0]), "r"((A)[1]), "r"((A)[2]), "r"((A)[3]), \
          "r"((B)[0]), "r"((B)[1]))
#define CP_ASYNC16(dst, src) \
    asm volatile("cp.async.cg.shared.global [%0], [%1], 16;" \
        :: "r"(dst), "l"(src))
#define CP_COMMIT() asm volatile("cp.async.commit_group;")
#define CP_WAIT(N)  asm volatile("cp.async.wait_group %0;" :: "n"(N))

// ===========================================================================
// Fused prep: TWO warps per row (hi pack + sq halves) | camid normalize
// ===========================================================================
__global__ void prep_fused_kernel(const float* __restrict__ f,
                                  const int* __restrict__ cam_raw,
                                  int n, int d, int rowBlocks) {
    int b = blockIdx.x;
    if (b < rowBlocks) {
        int wid  = threadIdx.x >> 5;
        int lane = threadIdx.x & 31;
        int row  = b * 4 + (wid >> 1);
        int half = wid & 1;
        if (row >= n) return;
        int idx = half * 32 + lane;                       // float4 index in row
        float4 x = ((const float4*)(f + (size_t)row * d))[idx];
        float s = x.x * x.x + x.y * x.y + x.z * x.z + x.w * x.w;
        __nv_bfloat162 h01(__float2bfloat16_rn(x.x), __float2bfloat16_rn(x.y));
        __nv_bfloat162 h23(__float2bfloat16_rn(x.z), __float2bfloat16_rn(x.w));
#pragma unroll
        for (int off = 16; off; off >>= 1) s += __shfl_down_sync(0xffffffffu, s, off);
        if (lane == 0) g_sq2[half][row] = s;

        uint2 hv = make_uint2(*(uint32_t*)&h01, *(uint32_t*)&h23);
        ((uint2*)(g_pa + (size_t)row * KPACK))[idx] = hv;
    } else {
        __shared__ int s_is64;
        int tid = threadIdx.x;
        if (tid < 32) {
            int nz = 0;
            if (4 * tid + 3 < 2 * n) {
                uint4 w = ((const uint4*)cam_raw)[tid];
                nz = (w.y != 0) || (w.w != 0);
            }
            unsigned bal = __ballot_sync(0xffffffffu, nz);
            if (tid == 0) { s_is64 = (bal == 0); g_ctr = 0; }
        }
        __syncthreads();
        int is64 = s_is64;
        for (int j = tid; j < n; j += blockDim.x)
            g_cam[j] = (unsigned char)(is64 ? cam_raw[2 * j] : cam_raw[j]);
    }
}

// ===========================================================================
// Distance GEMM via mma.sync bf16, UPPER-TRIANGLE blocks only. Pure hi
// product (K=256): dist^2 = sq_i + sq_j + eps - 2*hi_i.hi_j. Exact symmetry.
// ===========================================================================
#define NCHUNK (KPACK / 64)          // 4
#define BUF_BYTES 32768
#define TLDA 129
#define SMEM_GEMM_TOTAL (1024 + 3 * BUF_BYTES)

__global__ void __launch_bounds__(256, 2) dist_gemm_mma(int n) {
    extern __shared__ char smem_raw[];
    uint32_t sraw = smem_to_u32(smem_raw);
    uint32_t sbase = (sraw + 1023) & ~1023u;
    int tid = threadIdx.x, lane = tid & 31, wid = tid >> 5;

    int NB = n >> 7;
    int t = blockIdx.x;
    int bi = (int)((2.0f * NB + 1.0f -
                    sqrtf((2.0f * NB + 1.0f) * (2.0f * NB + 1.0f) - 8.0f * t)) * 0.5f);
    if (bi < 0) bi = 0;
    if (bi > NB - 1) bi = NB - 1;
#define TRI_START(r) ((r) * NB - ((r) * ((r) - 1)) / 2)
    while (bi + 1 < NB && TRI_START(bi + 1) <= t) ++bi;
    while (bi > 0 && TRI_START(bi) > t) --bi;
    int bj = bi + (t - TRI_START(bi));
#undef TRI_START

    const char* pa = (const char*)(g_pa + (size_t)bi * 128 * KPACK);
    const char* pb = (const char*)(g_pa + (size_t)bj * 128 * KPACK);
    const int ROWB = KPACK * 2;      // 512 bytes per row

    int seg = tid & 7, r0 = tid >> 3;

#define LOAD_CHUNK(c, buf) do { \
    uint32_t abase_ = sbase + (buf) * BUF_BYTES; \
    uint32_t bbase_ = abase_ + 16384; \
    _Pragma("unroll") \
    for (int it = 0; it < 4; ++it) { \
        int row = r0 + it * 32; \
        uint32_t off = row * 128 + seg * 16; \
        off = off ^ ((off >> 3) & 0x70); \
        CP_ASYNC16(abase_ + off, pa + (size_t)row * ROWB + (c) * 128 + seg * 16); \
        CP_ASYNC16(bbase_ + off, pb + (size_t)row * ROWB + (c) * 128 + seg * 16); \
    } \
    CP_COMMIT(); \
} while (0)

    int wr = wid >> 2, wc = wid & 3;
    int wm = wr * 64, wn = wc * 32;

    float acc[4][4][4];
#pragma unroll
    for (int mt = 0; mt < 4; ++mt)
#pragma unroll
        for (int nt = 0; nt < 4; ++nt)
#pragma unroll
            for (int e = 0; e < 4; ++e) acc[mt][nt][e] = 0.f;

    LOAD_CHUNK(0, 0);
    LOAD_CHUNK(1, 1);
    for (int c = 0; c < NCHUNK; ++c) {
        if (c == NCHUNK - 1) CP_WAIT(0);
        else                 CP_WAIT(1);
        __syncthreads();
        if (c + 2 < NCHUNK) LOAD_CHUNK(c + 2, (c + 2) % 3);

        uint32_t abase = sbase + (c % 3) * BUF_BYTES;
        uint32_t bbase = abase + 16384;
#pragma unroll
        for (int kk = 0; kk < 4; ++kk) {
            uint32_t afr[4][4], bfr[4][2];
#pragma unroll
            for (int mt = 0; mt < 4; ++mt) {
                int row = wm + mt * 16 + (lane & 15);
                uint32_t off = row * 128 + kk * 32 + (lane >> 4) * 16;
                off = off ^ ((off >> 3) & 0x70);
                LDMATRIX_X4(afr[mt], abase + off);
            }
#pragma unroll
            for (int np = 0; np < 2; ++np) {
                int row = wn + np * 16 + ((lane >> 4) << 3) + (lane & 7);
                uint32_t off = row * 128 + kk * 32 + (((lane >> 3) & 1) << 4);
                off = off ^ ((off >> 3) & 0x70);
                uint32_t q[4];
                LDMATRIX_X4(q, bbase + off);
                bfr[np * 2 + 0][0] = q[0]; bfr[np * 2 + 0][1] = q[1];
                bfr[np * 2 + 1][0] = q[2]; bfr[np * 2 + 1][1] = q[3];
            }
#pragma unroll
            for (int mt = 0; mt < 4; ++mt)
#pragma unroll
                for (int nt = 0; nt < 4; ++nt)
                    MMA_BF16(acc[mt][nt], afr[mt], bfr[nt]);
        }
    }

    __shared__ float ssq[256];
    float* s_tile = (float*)(smem_raw + (sbase - sraw));
    if (tid < 128) ssq[tid] = g_sq2[0][bi * 128 + tid] + g_sq2[1][bi * 128 + tid];
    else ssq[tid] = g_sq2[0][bj * 128 + (tid - 128)] + g_sq2[1][bj * 128 + (tid - 128)];
    __syncthreads();

    int g4 = lane >> 2, t4 = lane & 3;
#pragma unroll
    for (int mt = 0; mt < 4; ++mt) {
#pragma unroll
        for (int half = 0; half < 2; ++half) {
            int r = wm + mt * 16 + g4 + half * 8;
            int gi = bi * 128 + r;
            float sqi = ssq[r];
#pragma unroll
            for (int nt = 0; nt < 4; ++nt) {
                int col = wn + nt * 8 + 2 * t4;
                int gj = bj * 128 + col;
                float2 o;
                float d0 = sqi + ssq[128 + col] + EPS_F
                           - 2.0f * acc[mt][nt][half * 2 + 0];
                float d1 = sqi + ssq[128 + col + 1] + EPS_F
                           - 2.0f * acc[mt][nt][half * 2 + 1];
                o.x = sqrtf(fmaxf(d0, 1e-12f));
                o.y = sqrtf(fmaxf(d1, 1e-12f));
                if (gi == gj)     o.x = sqrtf(EPS_F);
                if (gi == gj + 1) o.y = sqrtf(EPS_F);
                *(float2*)(g_dist + (size_t)gi * n + gj) = o;
                s_tile[r * TLDA + col]     = o.x;
                s_tile[r * TLDA + col + 1] = o.y;
            }
        }
    }

    if (bi != bj) {
        __syncthreads();
#pragma unroll
        for (int it = 0; it < 16; ++it) {
            int c = it * 8 + wid;
            float* orow = g_dist + (size_t)(bj * 128 + c) * n + bi * 128;
#pragma unroll
            for (int q = 0; q < 4; ++q) {
                int r = lane + q * 32;
                orow[r] = s_tile[r * TLDA + c];
            }
        }
    }
#undef LOAD_CHUNK
}

// ===========================================================================
// Row kernel v6: two warps per row + explicit MLP=4 batching.
// ===========================================================================
template <int N>
__device__ __forceinline__ void insertN(float (&t)[N], float x) {
    if (x < t[N - 1]) {
        t[N - 1] = x;
#pragma unroll
        for (int k = N - 1; k > 0; --k) {
            float a = t[k - 1], b = t[k];
            t[k - 1] = fminf(a, b); t[k] = fmaxf(a, b);
        }
    }
}

template <int N>
__device__ __forceinline__ void warp_merge(float (&t)[N], int lane, float (&out)[N]) {
#pragma unroll
    for (int r = 0; r < N; ++r) {
        float bv = t[0]; int bl = lane;
#pragma unroll
        for (int off = 16; off; off >>= 1) {
            float ov = __shfl_down_sync(0xffffffffu, bv, off);
            int   ol = __shfl_down_sync(0xffffffffu, bl, off);
            if (ov < bv) { bv = ov; bl = ol; }
        }
        bv = __shfl_sync(0xffffffffu, bv, 0);
        bl = __shfl_sync(0xffffffffu, bl, 0);
        if (lane == bl) {
#pragma unroll
            for (int k = 0; k < N - 1; ++k) t[k] = t[k + 1];
            t[N - 1] = INF_F;
        }
        out[r] = bv;
    }
}

__device__ __forceinline__ float merged3(const float* A, const float* B) {
    float m = B[3];
    m = fminf(m, fmaxf(A[0], B[2]));
    m = fminf(m, fmaxf(A[1], B[1]));
    m = fminf(m, fmaxf(A[2], B[0]));
    m = fminf(m, A[3]);
    return m;
}
__device__ __forceinline__ float merged6(const float* A, const float* B) {
    float m = B[6];
    m = fminf(m, fmaxf(A[0], B[5]));
    m = fminf(m, fmaxf(A[1], B[4]));
    m = fminf(m, fmaxf(A[2], B[3]));
    m = fminf(m, fmaxf(A[3], B[2]));
    m = fminf(m, fmaxf(A[4], B[1]));
    m = fminf(m, fmaxf(A[5], B[0]));
    m = fminf(m, A[6]);
    return m;
}

__global__ void __launch_bounds__(256) row_kernel(int n, int nCtas,
                                                  float* __restrict__ out) {
    __shared__ unsigned char s_cam[NMAX];
    __shared__ float s_lists[8][12];
    __shared__ float s_sums[8][2];
    __shared__ float s_part[4];
    __shared__ float s_red[256];
    __shared__ int   s_last;

    int tid = threadIdx.x, wid = tid >> 5, lane = tid & 31;
    int rowLocal = wid >> 1, half = wid & 1;
    int row = blockIdx.x * 4 + rowLocal;

    for (int j = tid; j < n / 16; j += 256)
        ((uint4*)s_cam)[j] = ((const uint4*)g_cam)[j];
    __syncthreads();

    int mycam = s_cam[row];
    const float4* drow4 = (const float4*)(g_dist + (size_t)row * n);
    int itBeg = half * 16;

    float t4I[4], t7E[7];
#pragma unroll
    for (int k = 0; k < 4; ++k) t4I[k] = INF_F;
#pragma unroll
    for (int k = 0; k < 7; ++k) t7E[k] = INF_F;

    for (int base = itBeg; base < itBeg + 16; base += 4) {
        float4 f[4]; uchar4 c[4];
#pragma unroll
        for (int q = 0; q < 4; ++q) {
            int j4 = (base + q) * 32 + lane;
            f[q] = drow4[j4];
            c[q] = ((const uchar4*)s_cam)[j4];
        }
#pragma unroll
        for (int q = 0; q < 4; ++q) {
            int jb = ((base + q) * 32 + lane) << 2;
            float x0 = (jb     == row) ? INF_F : f[q].x;
            float x1 = (jb + 1 == row) ? INF_F : f[q].y;
            float x2 = (jb + 2 == row) ? INF_F : f[q].z;
            float x3 = (jb + 3 == row) ? INF_F : f[q].w;
            if (c[q].x == mycam) insertN<4>(t4I, x0); else insertN<7>(t7E, x0);
            if (c[q].y == mycam) insertN<4>(t4I, x1); else insertN<7>(t7E, x1);
            if (c[q].z == mycam) insertN<4>(t4I, x2); else insertN<7>(t7E, x2);
            if (c[q].w == mycam) insertN<4>(t4I, x3); else insertN<7>(t7E, x3);
        }
    }

    float mI[4], mEv[7];
    warp_merge<4>(t4I, lane, mI);
    warp_merge<7>(t7E, lane, mEv);
    if (lane == 0) {
        s_lists[wid][0] = mI[0];  s_lists[wid][1] = mI[1];
        s_lists[wid][2] = mI[2];  s_lists[wid][3] = mI[3];
        s_lists[wid][4] = mEv[0]; s_lists[wid][5] = mEv[1];
        s_lists[wid][6] = mEv[2]; s_lists[wid][7] = mEv[3];
        s_lists[wid][8] = mEv[4]; s_lists[wid][9] = mEv[5];
        s_lists[wid][10] = mEv[6];
    }
    __syncthreads();

    const float* LA = s_lists[rowLocal * 2];
    const float* LB = s_lists[rowLocal * 2 + 1];
    float dKi = merged3(LA, LB);
    float dKe = merged6(LA + 4, LB + 4);

    float si = 0.f, se = 0.f;
    for (int base = itBeg; base < itBeg + 16; base += 4) {
        float4 f[4]; uchar4 c[4];
#pragma unroll
        for (int q = 0; q < 4; ++q) {
            int j4 = (base + q) * 32 + lane;
            f[q] = drow4[j4];
            c[q] = ((const uchar4*)s_cam)[j4];
        }
#pragma unroll
        for (int q = 0; q < 4; ++q) {
            int jb = ((base + q) * 32 + lane) << 2;
            float x0 = (jb     == row) ? INF_F : f[q].x;
            float x1 = (jb + 1 == row) ? INF_F : f[q].y;
            float x2 = (jb + 2 == row) ? INF_F : f[q].z;
            float x3 = (jb + 3 == row) ? INF_F : f[q].w;
#define ACC1(cm, xx) do { \
            bool m_ = (cm == mycam); \
            float dk_ = m_ ? dKi : dKe; \
            float e_ = __expf(SCALE_F * (dk_ - (xx))); \
            e_ = ((xx) >= dk_) ? e_ : 0.f; \
            if (m_) si += e_; else se += e_; } while (0)
            ACC1(c[q].x, x0); ACC1(c[q].y, x1); ACC1(c[q].z, x2); ACC1(c[q].w, x3);
#undef ACC1
        }
    }
#pragma unroll
    for (int off = 16; off; off >>= 1) {
        si += __shfl_xor_sync(0xffffffffu, si, off);
        se += __shfl_xor_sync(0xffffffffu, se, off);
    }
    if (lane == 0) { s_sums[wid][0] = si; s_sums[wid][1] = se; }
    __syncthreads();

    if (tid < 4) {
        const float* A = s_lists[tid * 2];
        const float* B = s_lists[tid * 2 + 1];
        float dKi2 = merged3(A, B);
        float dKe2 = merged6(A + 4, B + 4);
        float d0e2 = fminf(A[4], B[4]);
        float Si = s_sums[tid * 2][0] + s_sums[tid * 2 + 1][0];
        float Se = s_sums[tid * 2][1] + s_sums[tid * 2 + 1][1];
        float term_i = 0.f, term_e = 0.f;
        if (isfinite(dKi2))
            term_i = fmaxf(SCALE_F * (sqrtf(EPS_F) - dKi2) + logf(Si) + 40.0f, 0.f);
        if (isfinite(dKe2))
            term_e = fmaxf(SCALE_F * (d0e2 - dKe2) + logf(Se) + 6.0f, 0.f);
        s_part[tid] = term_i + 0.5f * term_e;
    }
    __syncthreads();

    if (tid == 0) {
        float p = s_part[0] + s_part[1] + s_part[2] + s_part[3];
        g_partial[blockIdx.x] = p;
        __threadfence();
        int old = atomicAdd(&g_ctr, 1);
        s_last = (old == nCtas - 1);
    }
    __syncthreads();

    if (s_last) {
        float s = 0.f;
        for (int j = tid; j < nCtas; j += 256) s += g_partial[j];
        s_red[tid] = s;
        __syncthreads();
        for (int st = 128; st; st >>= 1) {
            if (tid < st) s_red[tid] += s_red[tid + st];
            __syncthreads();
        }
        if (tid == 0) { out[0] = s_red[0] / (float)n; g_ctr = 0; }
    }
}

// ===========================================================================
extern "C" void kernel_launch(void* const* d_in, const int* in_sizes, int n_in,
                              void* d_out, int out_size) {
    const float* feat = (const float*)d_in[0];
    const int*   cam  = (const int*)d_in[1];
    int n = in_sizes[1];
    int d = in_sizes[0] / n;
    int NB = n / 128;

    static int smem_set = 0;
    if (!smem_set) {
        cudaFuncSetAttribute(dist_gemm_mma,
                             cudaFuncAttributeMaxDynamicSharedMemorySize,
                             SMEM_GEMM_TOTAL);
        smem_set = 1;
    }

    int rowBlocks = (n + 3) / 4;
    prep_fused_kernel<<<rowBlocks + 1, 256>>>(feat, cam, n, d, rowBlocks);
    dist_gemm_mma<<<NB * (NB + 1) / 2, 256, SMEM_GEMM_TOTAL>>>(n);
    int nCtas = n / 4;
    row_kernel<<<nCtas, 256>>>(n, nCtas, (float*)d_out);
}

// round 17
// speedup vs baseline: 1.5784x; 1.0556x over previous
#include <cuda_runtime.h>
#include <cuda_bf16.h>
#include <math.h>
#include <stdint.h>

#define NMAX 4096
#define DMAX 256
#define KPACK 256              // pure hi pack; A = B (exact symmetry)
#define SCALE_F 10.0f
#define EPS_F 1e-5f
#define INF_F __int_as_float(0x7f800000)
#define QSCALE 2048.0f
#define QARG 0.0048828125f     // 10 / 2048
#define QSENT 0x7fffffff

__device__ unsigned short g_distq[(size_t)NMAX * NMAX];
__device__ float g_sq2[2][NMAX];
__device__ unsigned char g_cam[NMAX];
__device__ float g_partial[NMAX];
__device__ int g_ctr = 0;
__device__ __nv_bfloat16 g_pa[(size_t)NMAX * KPACK];

__device__ __forceinline__ uint32_t smem_to_u32(const void* p) {
    uint32_t a;
    asm("{ .reg .u64 t; cvta.to.shared.u64 t, %1; cvt.u32.u64 %0, t; }"
        : "=r"(a) : "l"(p));
    return a;
}

#define LDMATRIX_X4(R, addr) \
    asm volatile("ldmatrix.sync.aligned.m8n8.x4.shared.b16 {%0,%1,%2,%3}, [%4];" \
        : "=r"((R)[0]), "=r"((R)[1]), "=r"((R)[2]), "=r"((R)[3]) : "r"(addr))
#define MMA_BF16(D, A, B) \
    asm volatile("mma.sync.aligned.m16n8k16.row.col.f32.bf16.bf16.f32 " \
        "{%0,%1,%2,%3}, {%4,%5,%6,%7}, {%8,%9}, {%0,%1,%2,%3};" \
        : "+f"((D)[0]), "+f"((D)[1]), "+f"((D)[2]), "+f"((D)[3]) \
        : "r"((A)[0]), "r"((A)[1]), "r"((A)[2]), "r"((A)[3]), \
          "r"((B)[0]), "r"((B)[1]))
#define CP_ASYNC16(dst, src) \
    asm volatile("cp.async.cg.shared.global [%0], [%1], 16;" \
        :: "r"(dst), "l"(src))
#define CP_COMMIT() asm volatile("cp.async.commit_group;")
#define CP_WAIT(N)  asm volatile("cp.async.wait_group %0;" :: "n"(N))

// ===========================================================================
// Fused prep: TWO warps per row (hi pack + sq halves) | camid normalize
// ===========================================================================
__global__ void prep_fused_kernel(const float* __restrict__ f,
                                  const int* __restrict__ cam_raw,
                                  int n, int d, int rowBlocks) {
    int b = blockIdx.x;
    if (b < rowBlocks) {
        int wid  = threadIdx.x >> 5;
        int lane = threadIdx.x & 31;
        int row  = b * 4 + (wid >> 1);
        int half = wid & 1;
        if (row >= n) return;
        int idx = half * 32 + lane;
        float4 x = ((const float4*)(f + (size_t)row * d))[idx];
        float s = x.x * x.x + x.y * x.y + x.z * x.z + x.w * x.w;
        __nv_bfloat162 h01(__float2bfloat16_rn(x.x), __float2bfloat16_rn(x.y));
        __nv_bfloat162 h23(__float2bfloat16_rn(x.z), __float2bfloat16_rn(x.w));
#pragma unroll
        for (int off = 16; off; off >>= 1) s += __shfl_down_sync(0xffffffffu, s, off);
        if (lane == 0) g_sq2[half][row] = s;

        uint2 hv = make_uint2(*(uint32_t*)&h01, *(uint32_t*)&h23);
        ((uint2*)(g_pa + (size_t)row * KPACK))[idx] = hv;
    } else {
        __shared__ int s_is64;
        int tid = threadIdx.x;
        if (tid < 32) {
            int nz = 0;
            if (4 * tid + 3 < 2 * n) {
                uint4 w = ((const uint4*)cam_raw)[tid];
                nz = (w.y != 0) || (w.w != 0);
            }
            unsigned bal = __ballot_sync(0xffffffffu, nz);
            if (tid == 0) { s_is64 = (bal == 0); g_ctr = 0; }
        }
        __syncthreads();
        int is64 = s_is64;
        for (int j = tid; j < n; j += blockDim.x)
            g_cam[j] = (unsigned char)(is64 ? cam_raw[2 * j] : cam_raw[j]);
    }
}

// ===========================================================================
// Distance GEMM via mma.sync bf16, UPPER-TRIANGLE blocks, u16-quantized
// output (self = 65535 sentinel). dist^2 = sq_i + sq_j + eps - 2*hi.hi.
// ===========================================================================
#define NCHUNK (KPACK / 64)          // 4
#define BUF_BYTES 32768
#define TLDA2 130                    // u16 staging leading dim (conflict-free)
#define SMEM_GEMM_TOTAL (1024 + 3 * BUF_BYTES)

__global__ void __launch_bounds__(256, 2) dist_gemm_mma(int n) {
    extern __shared__ char smem_raw[];
    uint32_t sraw = smem_to_u32(smem_raw);
    uint32_t sbase = (sraw + 1023) & ~1023u;
    int tid = threadIdx.x, lane = tid & 31, wid = tid >> 5;

    int NB = n >> 7;
    int t = blockIdx.x;
    int bi = (int)((2.0f * NB + 1.0f -
                    sqrtf((2.0f * NB + 1.0f) * (2.0f * NB + 1.0f) - 8.0f * t)) * 0.5f);
    if (bi < 0) bi = 0;
    if (bi > NB - 1) bi = NB - 1;
#define TRI_START(r) ((r) * NB - ((r) * ((r) - 1)) / 2)
    while (bi + 1 < NB && TRI_START(bi + 1) <= t) ++bi;
    while (bi > 0 && TRI_START(bi) > t) --bi;
    int bj = bi + (t - TRI_START(bi));
#undef TRI_START

    const char* pa = (const char*)(g_pa + (size_t)bi * 128 * KPACK);
    const char* pb = (const char*)(g_pa + (size_t)bj * 128 * KPACK);
    const int ROWB = KPACK * 2;      // 512 bytes per row

    int seg = tid & 7, r0 = tid >> 3;

#define LOAD_CHUNK(c, buf) do { \
    uint32_t abase_ = sbase + (buf) * BUF_BYTES; \
    uint32_t bbase_ = abase_ + 16384; \
    _Pragma("unroll") \
    for (int it = 0; it < 4; ++it) { \
        int row = r0 + it * 32; \
        uint32_t off = row * 128 + seg * 16; \
        off = off ^ ((off >> 3) & 0x70); \
        CP_ASYNC16(abase_ + off, pa + (size_t)row * ROWB + (c) * 128 + seg * 16); \
        CP_ASYNC16(bbase_ + off, pb + (size_t)row * ROWB + (c) * 128 + seg * 16); \
    } \
    CP_COMMIT(); \
} while (0)

    int wr = wid >> 2, wc = wid & 3;
    int wm = wr * 64, wn = wc * 32;

    float acc[4][4][4];
#pragma unroll
    for (int mt = 0; mt < 4; ++mt)
#pragma unroll
        for (int nt = 0; nt < 4; ++nt)
#pragma unroll
            for (int e = 0; e < 4; ++e) acc[mt][nt][e] = 0.f;

    LOAD_CHUNK(0, 0);
    LOAD_CHUNK(1, 1);
    for (int c = 0; c < NCHUNK; ++c) {
        if (c == NCHUNK - 1) CP_WAIT(0);
        else                 CP_WAIT(1);
        __syncthreads();
        if (c + 2 < NCHUNK) LOAD_CHUNK(c + 2, (c + 2) % 3);

        uint32_t abase = sbase + (c % 3) * BUF_BYTES;
        uint32_t bbase = abase + 16384;
#pragma unroll
        for (int kk = 0; kk < 4; ++kk) {
            uint32_t afr[4][4], bfr[4][2];
#pragma unroll
            for (int mt = 0; mt < 4; ++mt) {
                int row = wm + mt * 16 + (lane & 15);
                uint32_t off = row * 128 + kk * 32 + (lane >> 4) * 16;
                off = off ^ ((off >> 3) & 0x70);
                LDMATRIX_X4(afr[mt], abase + off);
            }
#pragma unroll
            for (int np = 0; np < 2; ++np) {
                int row = wn + np * 16 + ((lane >> 4) << 3) + (lane & 7);
                uint32_t off = row * 128 + kk * 32 + (((lane >> 3) & 1) << 4);
                off = off ^ ((off >> 3) & 0x70);
                uint32_t q[4];
                LDMATRIX_X4(q, bbase + off);
                bfr[np * 2 + 0][0] = q[0]; bfr[np * 2 + 0][1] = q[1];
                bfr[np * 2 + 1][0] = q[2]; bfr[np * 2 + 1][1] = q[3];
            }
#pragma unroll
            for (int mt = 0; mt < 4; ++mt)
#pragma unroll
                for (int nt = 0; nt < 4; ++nt)
                    MMA_BF16(acc[mt][nt], afr[mt], bfr[nt]);
        }
    }

    __shared__ float ssq[256];
    unsigned short* s_tileq = (unsigned short*)(smem_raw + (sbase - sraw));
    if (tid < 128) ssq[tid] = g_sq2[0][bi * 128 + tid] + g_sq2[1][bi * 128 + tid];
    else ssq[tid] = g_sq2[0][bj * 128 + (tid - 128)] + g_sq2[1][bj * 128 + (tid - 128)];
    __syncthreads();

    int g4 = lane >> 2, t4 = lane & 3;
#pragma unroll
    for (int mt = 0; mt < 4; ++mt) {
#pragma unroll
        for (int half = 0; half < 2; ++half) {
            int r = wm + mt * 16 + g4 + half * 8;
            int gi = bi * 128 + r;
            float sqi = ssq[r];
#pragma unroll
            for (int nt = 0; nt < 4; ++nt) {
                int col = wn + nt * 8 + 2 * t4;
                int gj = bj * 128 + col;
                float d0 = sqi + ssq[128 + col] + EPS_F
                           - 2.0f * acc[mt][nt][half * 2 + 0];
                float d1 = sqi + ssq[128 + col + 1] + EPS_F
                           - 2.0f * acc[mt][nt][half * 2 + 1];
                float ox = sqrtf(fmaxf(d0, 1e-12f));
                float oy = sqrtf(fmaxf(d1, 1e-12f));
                int qx = min(__float2int_rn(ox * QSCALE), 65534);
                int qy = min(__float2int_rn(oy * QSCALE), 65534);
                if (gi == gj)     qx = 65535;   // self sentinel
                if (gi == gj + 1) qy = 65535;
                ushort2 st;
                st.x = (unsigned short)qx; st.y = (unsigned short)qy;
                *(ushort2*)(g_distq + (size_t)gi * n + gj) = st;
                s_tileq[r * TLDA2 + col]     = st.x;
                s_tileq[r * TLDA2 + col + 1] = st.y;
            }
        }
    }

    if (bi != bj) {
        __syncthreads();
#pragma unroll
        for (int it = 0; it < 16; ++it) {
            int c = it * 8 + wid;
            unsigned short* orow = g_distq + (size_t)(bj * 128 + c) * n + bi * 128;
#pragma unroll
            for (int q = 0; q < 4; ++q) {
                int r = lane + q * 32;
                orow[r] = s_tileq[r * TLDA2 + c];
            }
        }
    }
#undef LOAD_CHUNK
}

// ===========================================================================
// Row kernel v7: two warps per row, u16 loads (8 elems / 16B), integer-
// domain selection with exact ties, branchless expf sums.
// ===========================================================================
template <int N>
__device__ __forceinline__ void insertQ(int (&t)[N], int x) {
    if (x < t[N - 1]) {
        t[N - 1] = x;
#pragma unroll
        for (int k = N - 1; k > 0; --k) {
            int a = t[k - 1], b = t[k];
            t[k - 1] = min(a, b); t[k] = max(a, b);
        }
    }
}

template <int N>
__device__ __forceinline__ void warp_mergeQ(int (&t)[N], int lane, int (&out)[N]) {
#pragma unroll
    for (int r = 0; r < N; ++r) {
        int bv = t[0], bl = lane;
#pragma unroll
        for (int off = 16; off; off >>= 1) {
            int ov = __shfl_down_sync(0xffffffffu, bv, off);
            int ol = __shfl_down_sync(0xffffffffu, bl, off);
            if (ov < bv) { bv = ov; bl = ol; }
        }
        bv = __shfl_sync(0xffffffffu, bv, 0);
        bl = __shfl_sync(0xffffffffu, bl, 0);
        if (lane == bl) {
#pragma unroll
            for (int k = 0; k < N - 1; ++k) t[k] = t[k + 1];
            t[N - 1] = QSENT;
        }
        out[r] = bv;
    }
}

__device__ __forceinline__ int imerged3(const int* A, const int* B) {
    int m = B[3];
    m = min(m, max(A[0], B[2]));
    m = min(m, max(A[1], B[1]));
    m = min(m, max(A[2], B[0]));
    m = min(m, A[3]);
    return m;
}
__device__ __forceinline__ int imerged6(const int* A, const int* B) {
    int m = B[6];
    m = min(m, max(A[0], B[5]));
    m = min(m, max(A[1], B[4]));
    m = min(m, max(A[2], B[3]));
    m = min(m, max(A[3], B[2]));
    m = min(m, max(A[4], B[1]));
    m = min(m, max(A[5], B[0]));
    m = min(m, A[6]);
    return m;
}

__global__ void __launch_bounds__(256) row_kernel(int n, int nCtas,
                                                  float* __restrict__ out) {
    __shared__ unsigned char s_cam[NMAX];
    __shared__ int   s_lists[8][12];
    __shared__ float s_sums[8][2];
    __shared__ float s_part[4];
    __shared__ float s_red[256];
    __shared__ int   s_last;

    int tid = threadIdx.x, wid = tid >> 5, lane = tid & 31;
    int rowLocal = wid >> 1, half = wid & 1;
    int row = blockIdx.x * 4 + rowLocal;

    for (int j = tid; j < n / 16; j += 256)
        ((uint4*)s_cam)[j] = ((const uint4*)g_cam)[j];
    __syncthreads();

    int mycam = s_cam[row];
    const uint4* drowq = (const uint4*)(g_distq + (size_t)row * n);  // 8 elems
    int itBeg = half * 8;                      // 8 iters x 256 elems per half

    // ---- pass 1: guarded integer inserts (self auto-excluded via sentinel)
    int t4I[4], t7E[7];
#pragma unroll
    for (int k = 0; k < 4; ++k) t4I[k] = QSENT;
#pragma unroll
    for (int k = 0; k < 7; ++k) t7E[k] = QSENT;

    for (int base = itBeg; base < itBeg + 8; base += 4) {
        uint4 qv[4]; uint2 cv[4];
#pragma unroll
        for (int q = 0; q < 4; ++q) {
            int g = (base + q) * 32 + lane;
            qv[q] = drowq[g];
            cv[q] = ((const uint2*)s_cam)[g];
        }
#pragma unroll
        for (int q = 0; q < 4; ++q) {
            unsigned ws[4] = {qv[q].x, qv[q].y, qv[q].z, qv[q].w};
            unsigned cb[2] = {cv[q].x, cv[q].y};
#pragma unroll
            for (int e = 0; e < 4; ++e) {
                int qa = (int)(ws[e] & 0xffffu);
                int qb = (int)(ws[e] >> 16);
                int ca = (int)((cb[e >> 1] >> ((e & 1) * 16)) & 0xffu);
                int cbb = (int)((cb[e >> 1] >> ((e & 1) * 16 + 8)) & 0xffu);
                if (ca  == mycam) insertQ<4>(t4I, qa); else insertQ<7>(t7E, qa);
                if (cbb == mycam) insertQ<4>(t4I, qb); else insertQ<7>(t7E, qb);
            }
        }
    }

    int mI[4], mEv[7];
    warp_mergeQ<4>(t4I, lane, mI);
    warp_mergeQ<7>(t7E, lane, mEv);
    if (lane == 0) {
        s_lists[wid][0] = mI[0];  s_lists[wid][1] = mI[1];
        s_lists[wid][2] = mI[2];  s_lists[wid][3] = mI[3];
        s_lists[wid][4] = mEv[0]; s_lists[wid][5] = mEv[1];
        s_lists[wid][6] = mEv[2]; s_lists[wid][7] = mEv[3];
        s_lists[wid][8] = mEv[4]; s_lists[wid][9] = mEv[5];
        s_lists[wid][10] = mEv[6];
    }
    __syncthreads();

    const int* LA = s_lists[rowLocal * 2];
    const int* LB = s_lists[rowLocal * 2 + 1];
    int dKiq = imerged3(LA, LB);       // real intra rank 3 (self excluded)
    int dKeq = imerged6(LA + 4, LB + 4);
    int dkI = (dKiq <= 65534) ? dKiq : QSENT;   // invalid -> include nothing
    int dkE = (dKeq <= 65534) ? dKeq : QSENT;

    // ---- pass 2: branchless expf sums (sentinel q=65535 always excluded
    // when dk valid; q >= dk includes rank K + ties, corrected later)
    float si = 0.f, se = 0.f;
    for (int base = itBeg; base < itBeg + 8; base += 4) {
        uint4 qv[4]; uint2 cv[4];
#pragma unroll
        for (int q = 0; q < 4; ++q) {
            int g = (base + q) * 32 + lane;
            qv[q] = drowq[g];
            cv[q] = ((const uint2*)s_cam)[g];
        }
#pragma unroll
        for (int q = 0; q < 4; ++q) {
            unsigned ws[4] = {qv[q].x, qv[q].y, qv[q].z, qv[q].w};
            unsigned cb[2] = {cv[q].x, cv[q].y};
#pragma unroll
            for (int e = 0; e < 4; ++e) {
                int qa = (int)(ws[e] & 0xffffu);
                int qb = (int)(ws[e] >> 16);
                bool ma = ((int)((cb[e >> 1] >> ((e & 1) * 16)) & 0xffu) == mycam);
                bool mb = ((int)((cb[e >> 1] >> ((e & 1) * 16 + 8)) & 0xffu) == mycam);
                // sentinel 65535: include it only when dk valid (<=65534)? No:
                // qa==65535 >= dk would include exp(dk-65535)*QARG ~ exp(-big)=0. Safe.
                int da = (ma ? dkI : dkE) - qa;      // include iff da <= 0
                int db = (mb ? dkI : dkE) - qb;
                float ea = __expf((float)da * QARG);
                float eb = __expf((float)db * QARG);
                ea = (da <= 0) ? ea : 0.f;
                eb = (db <= 0) ? eb : 0.f;
                if (ma) si += ea; else se += ea;
                if (mb) si += eb; else se += eb;
            }
        }
    }
#pragma unroll
    for (int off = 16; off; off >>= 1) {
        si += __shfl_xor_sync(0xffffffffu, si, off);
        se += __shfl_xor_sync(0xffffffffu, se, off);
    }
    if (lane == 0) { s_sums[wid][0] = si; s_sums[wid][1] = se; }
    __syncthreads();

    if (tid < 4) {
        const int* A = s_lists[tid * 2];
        const int* B = s_lists[tid * 2 + 1];
        int dKi = imerged3(A, B);
        int dKe = imerged6(A + 4, B + 4);
        int d0e = min(A[4], B[4]);
        bool vI = dKi <= 65534, vE = dKe <= 65534;
        // tie corrections: c = K - #{union < dK} (all such elems are in lists)
        int lessI = (A[0] < dKi) + (A[1] < dKi) + (A[2] < dKi) + (A[3] < dKi)
                  + (B[0] < dKi) + (B[1] < dKi) + (B[2] < dKi) + (B[3] < dKi);
        int lessE = 0;
#pragma unroll
        for (int k = 4; k < 11; ++k) lessE += (A[k] < dKe) + (B[k] < dKe);
        float Si = s_sums[tid * 2][0] + s_sums[tid * 2 + 1][0] - (float)(3 - lessI);
        float Se = s_sums[tid * 2][1] + s_sums[tid * 2 + 1][1] - (float)(6 - lessE);
        float term_i = 0.f, term_e = 0.f;
        if (vI)
            term_i = fmaxf(SCALE_F * sqrtf(EPS_F) - (float)dKi * QARG
                           + logf(Si) + 40.0f, 0.f);
        if (vE)
            term_e = fmaxf((float)(d0e - dKe) * QARG + logf(Se) + 6.0f, 0.f);
        s_part[tid] = term_i + 0.5f * term_e;
    }
    __syncthreads();

    if (tid == 0) {
        float p = s_part[0] + s_part[1] + s_part[2] + s_part[3];
        g_partial[blockIdx.x] = p;
        __threadfence();
        int old = atomicAdd(&g_ctr, 1);
        s_last = (old == nCtas - 1);
    }
    __syncthreads();

    if (s_last) {
        float s = 0.f;
        for (int j = tid; j < nCtas; j += 256) s += g_partial[j];
        s_red[tid] = s;
        __syncthreads();
        for (int st = 128; st; st >>= 1) {
            if (tid < st) s_red[tid] += s_red[tid + st];
            __syncthreads();
        }
        if (tid == 0) { out[0] = s_red[0] / (float)n; g_ctr = 0; }
    }
}

// ===========================================================================
extern "C" void kernel_launch(void* const* d_in, const int* in_sizes, int n_in,
                              void* d_out, int out_size) {
    const float* feat = (const float*)d_in[0];
    const int*   cam  = (const int*)d_in[1];
    int n = in_sizes[1];
    int d = in_sizes[0] / n;
    int NB = n / 128;

    static int smem_set = 0;
    if (!smem_set) {
        cudaFuncSetAttribute(dist_gemm_mma,
                             cudaFuncAttributeMaxDynamicSharedMemorySize,
                             SMEM_GEMM_TOTAL);
        smem_set = 1;
    }

    int rowBlocks = (n + 3) / 4;
    prep_fused_kernel<<<rowBlocks + 1, 256>>>(feat, cam, n, d, rowBlocks);
    dist_gemm_mma<<<NB * (NB + 1) / 2, 256, SMEM_GEMM_TOTAL>>>(n);
    int nCtas = n / 4;
    row_kernel<<<nCtas, 256>>>(n, nCtas, (float*)d_out);
}